// round 1
// baseline (speedup 1.0000x reference)
#include <cuda_runtime.h>
#include <cstdint>

// ---------------------------------------------------------------------------
// Problem constants (shapes are fixed by the dataset)
// ---------------------------------------------------------------------------
constexpr int Bc = 8, Tc = 12, Nc = 512, Ec = 512, Dc = 512;
constexpr int BT = Bc * Tc;                 // 96
constexpr int GM = BT * Nc;                 // 49152 rows
constexpr int GK = 512;                     // inner dim
constexpr int GN = 512;                     // output dim
constexpr int KH = 8;                       // heads
constexpr int HD = 64;                      // head dim

// Scratch buffers (allocation-free rule: __device__ globals)
__device__ float g_q[(size_t)GM * Dc];
__device__ float g_k[(size_t)GM * Dc];
__device__ float g_v[(size_t)GM * Dc];
__device__ float g_o[(size_t)GM * Dc];
__device__ float g_h[(size_t)GM * Dc];

// ---------------------------------------------------------------------------
// f32x2 packed-FMA helpers (sm_100+: fma.rn.f32x2 doubles fp32 FMA rate)
// ---------------------------------------------------------------------------
typedef unsigned long long u64;

__device__ __forceinline__ u64 pack_dup(float a) {
    u64 r;
    asm("mov.b64 %0, {%1, %1};" : "=l"(r) : "f"(a));
    return r;
}
__device__ __forceinline__ void fma2(u64& acc, u64 a, u64 b) {
    asm("fma.rn.f32x2 %0, %1, %2, %0;" : "+l"(acc) : "l"(a), "l"(b));
}
__device__ __forceinline__ float2 unpack2(u64 v) {
    float lo, hi;
    asm("mov.b64 {%0, %1}, %2;" : "=f"(lo), "=f"(hi) : "l"(v));
    return make_float2(lo, hi);
}

// ---------------------------------------------------------------------------
// SGEMM: C[M,N] = act(A[M,K] @ W[K,N] + bias)
// BM=BN=128, BK=8, 256 threads, 8x8 per thread, f32x2 inner loop.
// gridDim.z selects among 3 (W, bias, out) sets -> fused QKV in one launch.
// ---------------------------------------------------------------------------
constexpr int BM = 128, BN = 128, BK = 8;

template <bool RELU>
__global__ __launch_bounds__(256)
void sgemm3(const float* __restrict__ A,
            const float* __restrict__ Wa, const float* __restrict__ Wb, const float* __restrict__ Wc,
            const float* __restrict__ ba, const float* __restrict__ bb, const float* __restrict__ bc,
            float* __restrict__ Oa, float* __restrict__ Ob, float* __restrict__ Oc)
{
    const int z = blockIdx.z;
    const float* W    = (z == 0) ? Wa : (z == 1) ? Wb : Wc;
    const float* bias = (z == 0) ? ba : (z == 1) ? bb : bc;
    float*       Cout = (z == 0) ? Oa : (z == 1) ? Ob : Oc;

    __shared__ float As[BK][BM];   // A tile transposed: As[k][m]
    __shared__ float Bs[BK][BN];   // W tile: Bs[k][n]

    const int tid   = threadIdx.x;
    const int mBase = blockIdx.y * BM;
    const int nBase = blockIdx.x * BN;

    // global-load mapping
    const int aRow = tid >> 1;               // 0..127
    const int aCol = (tid & 1) << 2;         // 0 or 4
    const int bRow = tid >> 5;               // 0..7
    const int bCol = (tid & 31) << 2;        // 0..124

    const float* Aptr = A + (size_t)(mBase + aRow) * GK + aCol;
    const float* Wptr = W + (size_t)bRow * GN + nBase + bCol;

    // compute mapping: 16x16 threads, each 8 rows x 8 cols
    const int tr = (tid >> 4) << 3;
    const int tc = (tid & 15) << 3;

    u64 acc[8][4];
#pragma unroll
    for (int i = 0; i < 8; i++)
#pragma unroll
        for (int j = 0; j < 4; j++) acc[i][j] = 0ULL;

    for (int kt = 0; kt < GK; kt += BK) {
        float4 av = *(const float4*)(Aptr + kt);
        float4 bv = *(const float4*)(Wptr + (size_t)kt * GN);
        As[aCol + 0][aRow] = av.x;
        As[aCol + 1][aRow] = av.y;
        As[aCol + 2][aRow] = av.z;
        As[aCol + 3][aRow] = av.w;
        *(float4*)&Bs[bRow][bCol] = bv;
        __syncthreads();

#pragma unroll
        for (int k = 0; k < BK; k++) {
            ulonglong2 bp0 = *(const ulonglong2*)&Bs[k][tc];
            ulonglong2 bp1 = *(const ulonglong2*)&Bs[k][tc + 4];
            float4 a0 = *(const float4*)&As[k][tr];
            float4 a1 = *(const float4*)&As[k][tr + 4];
            float ar[8] = {a0.x, a0.y, a0.z, a0.w, a1.x, a1.y, a1.z, a1.w};
#pragma unroll
            for (int i = 0; i < 8; i++) {
                u64 ad = pack_dup(ar[i]);
                fma2(acc[i][0], ad, bp0.x);
                fma2(acc[i][1], ad, bp0.y);
                fma2(acc[i][2], ad, bp1.x);
                fma2(acc[i][3], ad, bp1.y);
            }
        }
        __syncthreads();
    }

    // epilogue: bias (+ReLU) and coalesced stores
    float bcol[8];
#pragma unroll
    for (int j = 0; j < 8; j++) bcol[j] = bias[nBase + tc + j];

#pragma unroll
    for (int i = 0; i < 8; i++) {
        float c[8];
#pragma unroll
        for (int j2 = 0; j2 < 4; j2++) {
            float2 p = unpack2(acc[i][j2]);
            c[2 * j2]     = p.x;
            c[2 * j2 + 1] = p.y;
        }
#pragma unroll
        for (int j = 0; j < 8; j++) {
            c[j] += bcol[j];
            if (RELU) c[j] = fmaxf(c[j], 0.0f);
        }
        float* cp = Cout + (size_t)(mBase + tr + i) * GN + nBase + tc;
        *(float4*)(cp)     = make_float4(c[0], c[1], c[2], c[3]);
        *(float4*)(cp + 4) = make_float4(c[4], c[5], c[6], c[7]);
    }
}

// ---------------------------------------------------------------------------
// Attention: per CTA = one head (bt, kh) x 64 query rows.
// S = QK^T/8, P = exp(S)  (q,k>=0 after ReLU -> logits tiny -> no max-sub
// needed), accumulate O_unnorm += P*V and rowsum += P in ONE streaming pass,
// normalize at the end. Matches softmax exactly in exact arithmetic.
// ---------------------------------------------------------------------------
constexpr int PADR = 68;  // row pad (floats), keeps 16B alignment, kills conflicts
constexpr int ATT_SMEM_FLOATS = 4 * 64 * PADR + 64 * 17 + 64;
constexpr int ATT_SMEM_BYTES  = ATT_SMEM_FLOATS * 4;

__device__ __forceinline__ void load_tile_T(float (*dst)[PADR], const float* __restrict__ g, int tid) {
#pragma unroll
    for (int it = 0; it < 4; it++) {
        int idx = tid + it * 256;
        int r = idx >> 4;
        int c = (idx & 15) << 2;
        float4 v = *(const float4*)(g + (size_t)r * Dc + c);
        dst[c + 0][r] = v.x;
        dst[c + 1][r] = v.y;
        dst[c + 2][r] = v.z;
        dst[c + 3][r] = v.w;
    }
}
__device__ __forceinline__ void load_tile_D(float (*dst)[PADR], const float* __restrict__ g, int tid) {
#pragma unroll
    for (int it = 0; it < 4; it++) {
        int idx = tid + it * 256;
        int r = idx >> 4;
        int c = (idx & 15) << 2;
        float4 v = *(const float4*)(g + (size_t)r * Dc + c);
        *(float4*)&dst[r][c] = v;
    }
}

__global__ __launch_bounds__(256)
void attn_kernel(const float* __restrict__ Q, const float* __restrict__ Kg_,
                 const float* __restrict__ V, float* __restrict__ O)
{
    extern __shared__ float sm[];
    float (*Qt)[PADR] = (float(*)[PADR])(sm);                    // Qt[dd][n]
    float (*Kt)[PADR] = (float(*)[PADR])(sm + 64 * PADR);        // Kt[dd][m]
    float (*Vs)[PADR] = (float(*)[PADR])(sm + 2 * 64 * PADR);    // Vs[m][dd]
    float (*Pt)[PADR] = (float(*)[PADR])(sm + 3 * 64 * PADR);    // Pt[m][n]
    float (*rs)[17]   = (float(*)[17])  (sm + 4 * 64 * PADR);
    float* rinv       = sm + 4 * 64 * PADR + 64 * 17;

    const int tid  = threadIdx.x;
    const int head = blockIdx.x;          // 0..767
    const int bt   = head >> 3;
    const int kh   = head & 7;
    const size_t base = (size_t)bt * Nc * Dc + (size_t)kh * HD;

    const float* Qg = Q   + base + (size_t)(blockIdx.y * 64) * Dc;
    const float* Kg = Kg_ + base;
    const float* Vg = V   + base;
    float*       Og = O   + base + (size_t)(blockIdx.y * 64) * Dc;

    const int ty = tid >> 4;   // 0..15 -> rows n = ty*4 + i
    const int tx = tid & 15;   // 0..15 -> cols m/dd = tx*4 + j

    load_tile_T(Qt, Qg, tid);

    float partial[4] = {0.f, 0.f, 0.f, 0.f};
    u64 oacc[4][2];
#pragma unroll
    for (int i = 0; i < 4; i++) { oacc[i][0] = 0ULL; oacc[i][1] = 0ULL; }

    for (int mt = 0; mt < 8; mt++) {
        __syncthreads();  // Qt ready (mt=0) / prior P*V done (mt>0)
        load_tile_T(Kt, Kg + (size_t)mt * 64 * Dc, tid);
        load_tile_D(Vs, Vg + (size_t)mt * 64 * Dc, tid);
        __syncthreads();

        // --- S tile: S[n][m] = sum_dd Qt[dd][n] * Kt[dd][m] ---
        u64 sacc[4][2];
#pragma unroll
        for (int i = 0; i < 4; i++) { sacc[i][0] = 0ULL; sacc[i][1] = 0ULL; }
#pragma unroll 8
        for (int dd = 0; dd < 64; dd++) {
            ulonglong2 kv = *(const ulonglong2*)&Kt[dd][tx * 4];
            float4 qv = *(const float4*)&Qt[dd][ty * 4];
            float qa[4] = {qv.x, qv.y, qv.z, qv.w};
#pragma unroll
            for (int i = 0; i < 4; i++) {
                u64 qd = pack_dup(qa[i]);
                fma2(sacc[i][0], qd, kv.x);
                fma2(sacc[i][1], qd, kv.y);
            }
        }

        // --- exp, rowsum partials, stage P transposed ---
        float ex[4][4];
#pragma unroll
        for (int i = 0; i < 4; i++) {
            float2 p0 = unpack2(sacc[i][0]);
            float2 p1 = unpack2(sacc[i][1]);
            float e0 = __expf(p0.x * 0.125f);
            float e1 = __expf(p0.y * 0.125f);
            float e2 = __expf(p1.x * 0.125f);
            float e3 = __expf(p1.y * 0.125f);
            ex[i][0] = e0; ex[i][1] = e1; ex[i][2] = e2; ex[i][3] = e3;
            partial[i] += (e0 + e1) + (e2 + e3);
        }
#pragma unroll
        for (int j = 0; j < 4; j++)
            *(float4*)&Pt[tx * 4 + j][ty * 4] =
                make_float4(ex[0][j], ex[1][j], ex[2][j], ex[3][j]);
        __syncthreads();

        // --- O += P * V : O[n][dd] += Pt[m][n] * Vs[m][dd] ---
#pragma unroll 8
        for (int m = 0; m < 64; m++) {
            ulonglong2 vv = *(const ulonglong2*)&Vs[m][tx * 4];
            float4 pv = *(const float4*)&Pt[m][ty * 4];
            float pa[4] = {pv.x, pv.y, pv.z, pv.w};
#pragma unroll
            for (int i = 0; i < 4; i++) {
                u64 pd = pack_dup(pa[i]);
                fma2(oacc[i][0], pd, vv.x);
                fma2(oacc[i][1], pd, vv.y);
            }
        }
    }

    // --- rowsum reduction across the 16 tx threads of each row ---
    __syncthreads();
#pragma unroll
    for (int i = 0; i < 4; i++) rs[ty * 4 + i][tx] = partial[i];
    __syncthreads();
    if (tid < 64) {
        float s = 0.f;
#pragma unroll
        for (int t = 0; t < 16; t++) s += rs[tid][t];
        rinv[tid] = 1.0f / s;
    }
    __syncthreads();

    // --- normalize + write ---
#pragma unroll
    for (int i = 0; i < 4; i++) {
        float r = rinv[ty * 4 + i];
        float2 a = unpack2(oacc[i][0]);
        float2 b = unpack2(oacc[i][1]);
        *(float4*)&Og[(size_t)(ty * 4 + i) * Dc + tx * 4] =
            make_float4(a.x * r, a.y * r, b.x * r, b.y * r);
    }
}

// ---------------------------------------------------------------------------
// Launch
// ---------------------------------------------------------------------------
extern "C" void kernel_launch(void* const* d_in, const int* in_sizes, int n_in,
                              void* d_out, int out_size)
{
    (void)in_sizes; (void)n_in; (void)out_size;
    const float* X  = (const float*)d_in[0];
    // d_in[1] = STE (unused by reference)
    const float* Wq = (const float*)d_in[2];
    const float* bq = (const float*)d_in[3];
    const float* Wk = (const float*)d_in[4];
    const float* bk = (const float*)d_in[5];
    const float* Wv = (const float*)d_in[6];
    const float* bv = (const float*)d_in[7];
    const float* W1 = (const float*)d_in[8];
    const float* b1 = (const float*)d_in[9];
    const float* W2 = (const float*)d_in[10];
    const float* b2 = (const float*)d_in[11];
    float* out = (float*)d_out;

    float *q, *k, *v, *o, *h;
    cudaGetSymbolAddress((void**)&q, g_q);
    cudaGetSymbolAddress((void**)&k, g_k);
    cudaGetSymbolAddress((void**)&v, g_v);
    cudaGetSymbolAddress((void**)&o, g_o);
    cudaGetSymbolAddress((void**)&h, g_h);

    cudaFuncSetAttribute(attn_kernel, cudaFuncAttributeMaxDynamicSharedMemorySize,
                         ATT_SMEM_BYTES);

    dim3 blk(256);
    dim3 gQKV(GN / BN, GM / BM, 3);   // (4, 384, 3)
    dim3 gFC(GN / BN, GM / BM, 1);    // (4, 384)
    dim3 gAtt(BT * KH, Nc / 64);      // (768, 8)

    // 1) q,k,v = relu(X @ W + b)   (fused triple GEMM)
    sgemm3<true><<<gQKV, blk>>>(X, Wq, Wk, Wv, bq, bk, bv, q, k, v);
    // 2) attention per head
    attn_kernel<<<gAtt, blk, ATT_SMEM_BYTES>>>(q, k, v, o);
    // 3) h = relu(o @ W1 + b1)
    sgemm3<true><<<gFC, blk>>>(o, W1, W1, W1, b1, b1, b1, h, h, h);
    // 4) out = h @ W2 + b2
    sgemm3<false><<<gFC, blk>>>(h, W2, W2, W2, b2, b2, b2, out, out, out);
}

// round 3
// speedup vs baseline: 1.5655x; 1.5655x over previous
#include <cuda_runtime.h>
#include <cuda_bf16.h>
#include <cstdint>

// ---------------------------------------------------------------------------
// Problem constants
// ---------------------------------------------------------------------------
constexpr int Bc = 8, Tc = 12, Nc = 512, Dc = 512;
constexpr int BT = Bc * Tc;                 // 96
constexpr int GM = BT * Nc;                 // 49152 rows
constexpr int GK = 512;                     // logical inner dim
constexpr int GN = 512;                     // output dim
constexpr int KH = 8;                       // heads
constexpr int HD = 64;                      // head dim
constexpr int KEXP = 3 * GK;                // 1536 split-expanded K

// Scratch (allocation-free rule: __device__ globals)
__device__ float          g_q[(size_t)GM * Dc];
__device__ float          g_k[(size_t)GM * Dc];
__device__ float          g_v[(size_t)GM * Dc];
__device__ float          g_o[(size_t)GM * Dc];
__device__ __nv_bfloat16  g_a3[(size_t)GM * KEXP];       // split activations
__device__ __nv_bfloat16  g_w3[5 * (size_t)GN * KEXP];   // split weights, [n][k]

typedef unsigned long long u64;

__device__ __forceinline__ uint32_t smem_to_u32(const void* p) {
    uint32_t a;
    asm("{ .reg .u64 t; cvta.to.shared.u64 t, %1; cvt.u32.u64 %0, t; }" : "=r"(a) : "l"(p));
    return a;
}

// ---------------------------------------------------------------------------
// Portable tensor-core primitives (sm_80+ ISA; runs on Blackwell HMMA pipe)
// ---------------------------------------------------------------------------
__device__ __forceinline__ void ldsm_x4(uint32_t& r0, uint32_t& r1, uint32_t& r2, uint32_t& r3,
                                        uint32_t addr) {
    asm volatile("ldmatrix.sync.aligned.m8n8.x4.shared.b16 {%0,%1,%2,%3}, [%4];"
                 : "=r"(r0), "=r"(r1), "=r"(r2), "=r"(r3) : "r"(addr));
}
__device__ __forceinline__ void mma16816(float* d, const uint32_t* a, const uint32_t* b) {
    asm volatile("mma.sync.aligned.m16n8k16.row.col.f32.bf16.bf16.f32 "
                 "{%0,%1,%2,%3}, {%4,%5,%6,%7}, {%8,%9}, {%0,%1,%2,%3};"
                 : "+f"(d[0]), "+f"(d[1]), "+f"(d[2]), "+f"(d[3])
                 : "r"(a[0]), "r"(a[1]), "r"(a[2]), "r"(a[3]), "r"(b[0]), "r"(b[1]));
}
__device__ __forceinline__ void cp_async16(uint32_t smem_addr, const void* gptr) {
    asm volatile("cp.async.cg.shared.global [%0], [%1], 16;" :: "r"(smem_addr), "l"(gptr));
}
#define CP_COMMIT() asm volatile("cp.async.commit_group;" ::: "memory")
#define CP_WAIT(n)  asm volatile("cp.async.wait_group %0;" :: "n"(n) : "memory")

// ---------------------------------------------------------------------------
// Split-precision conversion kernels
// ---------------------------------------------------------------------------
__device__ __forceinline__ void split_bf16(float x, __nv_bfloat16& h, __nv_bfloat16& l) {
    h = __float2bfloat16_rn(x);
    l = __float2bfloat16_rn(x - __bfloat162float(h));
}

// A[M,512] fp32 -> A3[M,1536] bf16 laid out [Ah | Al | Ah]
__global__ __launch_bounds__(256) void conv_act(const float* __restrict__ A,
                                                __nv_bfloat16* __restrict__ A3) {
    size_t i = (size_t)blockIdx.x * 256 + threadIdx.x;   // over GM*128
    size_t row = i >> 7;
    int c4 = (int)(i & 127) << 2;
    float4 a = *(const float4*)(A + (row << 9) + c4);
    __nv_bfloat16 h[4], l[4];
    split_bf16(a.x, h[0], l[0]); split_bf16(a.y, h[1], l[1]);
    split_bf16(a.z, h[2], l[2]); split_bf16(a.w, h[3], l[3]);
    __nv_bfloat16* dst = A3 + row * KEXP + c4;
    *(uint2*)(dst)        = *(uint2*)h;
    *(uint2*)(dst + 512)  = *(uint2*)l;
    *(uint2*)(dst + 1024) = *(uint2*)h;
}

// W[512,512] fp32 (k-major) -> W3T[512 n-rows][1536] bf16 laid out [Wh | Wh | Wl]
__global__ __launch_bounds__(256) void conv_w(const float* __restrict__ W,
                                              __nv_bfloat16* __restrict__ W3T) {
    int i = blockIdx.x * 256 + threadIdx.x;   // 512*512
    int k = i >> 9, n = i & 511;
    __nv_bfloat16 h, l;
    split_bf16(W[i], h, l);
    __nv_bfloat16* dst = W3T + (size_t)n * KEXP + k;
    dst[0]    = h;
    dst[512]  = h;
    dst[1024] = l;
}

// ---------------------------------------------------------------------------
// HMMA GEMM: C[M,N] = act(A3[M,1536] @ W3T[N,1536]^T + bias), fp32 out
// CTA 128x128xBK32, 8 warps (2x4), warp tile 64x32, 2-stage cp.async.
// ---------------------------------------------------------------------------
constexpr int BM = 128, BN = 128, BK = 32;
constexpr int KST = 40;                      // padded smem stride (bf16 elems)
constexpr int NIT = KEXP / BK;               // 48

template <bool RELU>
__global__ __launch_bounds__(256)
void gemm_mma(const __nv_bfloat16* __restrict__ A3,
              const __nv_bfloat16* __restrict__ B0, const __nv_bfloat16* __restrict__ B1,
              const __nv_bfloat16* __restrict__ B2,
              const float* __restrict__ bias0, const float* __restrict__ bias1,
              const float* __restrict__ bias2,
              float* __restrict__ O0, float* __restrict__ O1, float* __restrict__ O2)
{
    const int z = blockIdx.z;
    const __nv_bfloat16* Bw = (z == 0) ? B0 : (z == 1) ? B1 : B2;
    const float* bias       = (z == 0) ? bias0 : (z == 1) ? bias1 : bias2;
    float* Out              = (z == 0) ? O0 : (z == 1) ? O1 : O2;

    __shared__ __nv_bfloat16 sA[2][BM * KST];
    __shared__ __nv_bfloat16 sB[2][BN * KST];

    const int tid = threadIdx.x;
    const int wid = tid >> 5;
    const int lid = tid & 31;
    const int warp_m = wid >> 2;         // 0..1
    const int warp_n = wid & 3;          // 0..3
    const int m0 = warp_m * 64;
    const int n0 = warp_n * 32;

    const size_t mBase = (size_t)blockIdx.y * BM;
    const size_t nBase = (size_t)blockIdx.x * BN;
    const __nv_bfloat16* Ag = A3 + mBase * KEXP;
    const __nv_bfloat16* Bg = Bw + nBase * KEXP;

    const uint32_t sAu = smem_to_u32(sA);
    const uint32_t sBu = smem_to_u32(sB);

    // per-thread staging indices: 512 16B-chunks per tile, 2 per thread
    const int ldr = tid >> 2;            // 0..63 base row
    const int ldu = (tid & 3) * 8;       // col element offset

    auto load_stage = [&](int buf, int it) {
        const int k0 = it * BK;
#pragma unroll
        for (int p = 0; p < 2; p++) {
            int r = ldr + p * 64;
            uint32_t soff = (uint32_t)((r * KST + ldu) * 2);
            cp_async16(sAu + (uint32_t)(buf * BM * KST * 2) + soff, Ag + (size_t)r * KEXP + k0 + ldu);
            cp_async16(sBu + (uint32_t)(buf * BN * KST * 2) + soff, Bg + (size_t)r * KEXP + k0 + ldu);
        }
        CP_COMMIT();
    };

    float acc[4][4][4];
#pragma unroll
    for (int i = 0; i < 4; i++)
#pragma unroll
        for (int j = 0; j < 4; j++)
#pragma unroll
            for (int c = 0; c < 4; c++) acc[i][j][c] = 0.0f;

    // ldmatrix lane addressing
    const int seg = lid >> 3, lrow = lid & 7;
    const int a_roff = lrow + ((seg & 1) << 3);
    const int a_coff = (seg >> 1) << 3;
    const int b_roff = lrow + ((seg >> 1) << 3);
    const int b_coff = (seg & 1) << 3;

    load_stage(0, 0);

    for (int it = 0; it < NIT; ++it) {
        const int buf = it & 1;
        if (it + 1 < NIT) {
            load_stage(buf ^ 1, it + 1);
            CP_WAIT(1);
        } else {
            CP_WAIT(0);
        }
        __syncthreads();

        const uint32_t aB = sAu + (uint32_t)(buf * BM * KST * 2);
        const uint32_t bB = sBu + (uint32_t)(buf * BN * KST * 2);

#pragma unroll
        for (int kk = 0; kk < 2; kk++) {
            uint32_t ra[4][4], rb[2][4];
#pragma unroll
            for (int mi = 0; mi < 4; mi++) {
                uint32_t addr = aB + (uint32_t)(((m0 + mi * 16 + a_roff) * KST + kk * 16 + a_coff) * 2);
                ldsm_x4(ra[mi][0], ra[mi][1], ra[mi][2], ra[mi][3], addr);
            }
#pragma unroll
            for (int nj = 0; nj < 2; nj++) {
                uint32_t addr = bB + (uint32_t)(((n0 + nj * 16 + b_roff) * KST + kk * 16 + b_coff) * 2);
                ldsm_x4(rb[nj][0], rb[nj][1], rb[nj][2], rb[nj][3], addr);
            }
#pragma unroll
            for (int mi = 0; mi < 4; mi++)
#pragma unroll
                for (int nj = 0; nj < 4; nj++)
                    mma16816(acc[mi][nj], ra[mi], &rb[nj >> 1][(nj & 1) * 2]);
        }
        __syncthreads();
    }

    // epilogue
    const int gr = lid >> 2;
    const int gc = (lid & 3) * 2;
#pragma unroll
    for (int mi = 0; mi < 4; mi++) {
        const size_t row0 = mBase + m0 + mi * 16 + gr;
#pragma unroll
        for (int nj = 0; nj < 4; nj++) {
            const int col = (int)nBase + n0 + nj * 8 + gc;
            const float bx = __ldg(&bias[col]);
            const float by = __ldg(&bias[col + 1]);
            float v0 = acc[mi][nj][0] + bx;
            float v1 = acc[mi][nj][1] + by;
            float v2 = acc[mi][nj][2] + bx;
            float v3 = acc[mi][nj][3] + by;
            if (RELU) {
                v0 = fmaxf(v0, 0.f); v1 = fmaxf(v1, 0.f);
                v2 = fmaxf(v2, 0.f); v3 = fmaxf(v3, 0.f);
            }
            *(float2*)(Out + row0 * GN + col)       = make_float2(v0, v1);
            *(float2*)(Out + (row0 + 8) * GN + col) = make_float2(v2, v3);
        }
    }
}

// ---------------------------------------------------------------------------
// Attention (fp32 f32x2) — unchanged (proven correct, Round 1)
// ---------------------------------------------------------------------------
__device__ __forceinline__ u64 pack_dup(float a) {
    u64 r; asm("mov.b64 %0, {%1, %1};" : "=l"(r) : "f"(a)); return r;
}
__device__ __forceinline__ void fma2(u64& acc, u64 a, u64 b) {
    asm("fma.rn.f32x2 %0, %1, %2, %0;" : "+l"(acc) : "l"(a), "l"(b));
}
__device__ __forceinline__ float2 unpack2(u64 v) {
    float lo, hi; asm("mov.b64 {%0, %1}, %2;" : "=f"(lo), "=f"(hi) : "l"(v));
    return make_float2(lo, hi);
}

constexpr int PADR = 68;
constexpr int ATT_SMEM_FLOATS = 4 * 64 * PADR + 64 * 17 + 64;
constexpr int ATT_SMEM_BYTES  = ATT_SMEM_FLOATS * 4;

__device__ __forceinline__ void load_tile_T(float (*dst)[PADR], const float* __restrict__ g, int tid) {
#pragma unroll
    for (int it = 0; it < 4; it++) {
        int idx = tid + it * 256;
        int r = idx >> 4;
        int c = (idx & 15) << 2;
        float4 v = *(const float4*)(g + (size_t)r * Dc + c);
        dst[c + 0][r] = v.x; dst[c + 1][r] = v.y; dst[c + 2][r] = v.z; dst[c + 3][r] = v.w;
    }
}
__device__ __forceinline__ void load_tile_D(float (*dst)[PADR], const float* __restrict__ g, int tid) {
#pragma unroll
    for (int it = 0; it < 4; it++) {
        int idx = tid + it * 256;
        int r = idx >> 4;
        int c = (idx & 15) << 2;
        float4 v = *(const float4*)(g + (size_t)r * Dc + c);
        *(float4*)&dst[r][c] = v;
    }
}

__global__ __launch_bounds__(256)
void attn_kernel(const float* __restrict__ Q, const float* __restrict__ Kg_,
                 const float* __restrict__ V, float* __restrict__ O)
{
    extern __shared__ float sm[];
    float (*Qt)[PADR] = (float(*)[PADR])(sm);
    float (*Kt)[PADR] = (float(*)[PADR])(sm + 64 * PADR);
    float (*Vs)[PADR] = (float(*)[PADR])(sm + 2 * 64 * PADR);
    float (*Pt)[PADR] = (float(*)[PADR])(sm + 3 * 64 * PADR);
    float (*rs)[17]   = (float(*)[17])  (sm + 4 * 64 * PADR);
    float* rinv       = sm + 4 * 64 * PADR + 64 * 17;

    const int tid  = threadIdx.x;
    const int head = blockIdx.x;
    const int bt   = head >> 3;
    const int kh   = head & 7;
    const size_t base = (size_t)bt * Nc * Dc + (size_t)kh * HD;

    const float* Qg = Q   + base + (size_t)(blockIdx.y * 64) * Dc;
    const float* Kg = Kg_ + base;
    const float* Vg = V   + base;
    float*       Og = O   + base + (size_t)(blockIdx.y * 64) * Dc;

    const int ty = tid >> 4;
    const int tx = tid & 15;

    load_tile_T(Qt, Qg, tid);

    float partial[4] = {0.f, 0.f, 0.f, 0.f};
    u64 oacc[4][2];
#pragma unroll
    for (int i = 0; i < 4; i++) { oacc[i][0] = 0ULL; oacc[i][1] = 0ULL; }

    for (int mt = 0; mt < 8; mt++) {
        __syncthreads();
        load_tile_T(Kt, Kg + (size_t)mt * 64 * Dc, tid);
        load_tile_D(Vs, Vg + (size_t)mt * 64 * Dc, tid);
        __syncthreads();

        u64 sacc[4][2];
#pragma unroll
        for (int i = 0; i < 4; i++) { sacc[i][0] = 0ULL; sacc[i][1] = 0ULL; }
#pragma unroll 8
        for (int dd = 0; dd < 64; dd++) {
            ulonglong2 kv = *(const ulonglong2*)&Kt[dd][tx * 4];
            float4 qv = *(const float4*)&Qt[dd][ty * 4];
            float qa[4] = {qv.x, qv.y, qv.z, qv.w};
#pragma unroll
            for (int i = 0; i < 4; i++) {
                u64 qd = pack_dup(qa[i]);
                fma2(sacc[i][0], qd, kv.x);
                fma2(sacc[i][1], qd, kv.y);
            }
        }

        float ex[4][4];
#pragma unroll
        for (int i = 0; i < 4; i++) {
            float2 p0 = unpack2(sacc[i][0]);
            float2 p1 = unpack2(sacc[i][1]);
            float e0 = __expf(p0.x * 0.125f);
            float e1 = __expf(p0.y * 0.125f);
            float e2 = __expf(p1.x * 0.125f);
            float e3 = __expf(p1.y * 0.125f);
            ex[i][0] = e0; ex[i][1] = e1; ex[i][2] = e2; ex[i][3] = e3;
            partial[i] += (e0 + e1) + (e2 + e3);
        }
#pragma unroll
        for (int j = 0; j < 4; j++)
            *(float4*)&Pt[tx * 4 + j][ty * 4] =
                make_float4(ex[0][j], ex[1][j], ex[2][j], ex[3][j]);
        __syncthreads();

#pragma unroll 8
        for (int m = 0; m < 64; m++) {
            ulonglong2 vv = *(const ulonglong2*)&Vs[m][tx * 4];
            float4 pv = *(const float4*)&Pt[m][ty * 4];
            float pa[4] = {pv.x, pv.y, pv.z, pv.w};
#pragma unroll
            for (int i = 0; i < 4; i++) {
                u64 pd = pack_dup(pa[i]);
                fma2(oacc[i][0], pd, vv.x);
                fma2(oacc[i][1], pd, vv.y);
            }
        }
    }

    __syncthreads();
#pragma unroll
    for (int i = 0; i < 4; i++) rs[ty * 4 + i][tx] = partial[i];
    __syncthreads();
    if (tid < 64) {
        float sum = 0.f;
#pragma unroll
        for (int t = 0; t < 16; t++) sum += rs[tid][t];
        rinv[tid] = 1.0f / sum;
    }
    __syncthreads();

#pragma unroll
    for (int i = 0; i < 4; i++) {
        float r = rinv[ty * 4 + i];
        float2 a = unpack2(oacc[i][0]);
        float2 b = unpack2(oacc[i][1]);
        *(float4*)&Og[(size_t)(ty * 4 + i) * Dc + tx * 4] =
            make_float4(a.x * r, a.y * r, b.x * r, b.y * r);
    }
}

// ---------------------------------------------------------------------------
// Launch
// ---------------------------------------------------------------------------
extern "C" void kernel_launch(void* const* d_in, const int* in_sizes, int n_in,
                              void* d_out, int out_size)
{
    (void)in_sizes; (void)n_in; (void)out_size;
    const float* X  = (const float*)d_in[0];
    const float* Wq = (const float*)d_in[2];
    const float* bq = (const float*)d_in[3];
    const float* Wk = (const float*)d_in[4];
    const float* bk = (const float*)d_in[5];
    const float* Wv = (const float*)d_in[6];
    const float* bv = (const float*)d_in[7];
    const float* W1 = (const float*)d_in[8];
    const float* b1 = (const float*)d_in[9];
    const float* W2 = (const float*)d_in[10];
    const float* b2 = (const float*)d_in[11];
    float* out = (float*)d_out;

    float *q, *k, *v, *o;
    __nv_bfloat16 *a3, *w3;
    cudaGetSymbolAddress((void**)&q,  g_q);
    cudaGetSymbolAddress((void**)&k,  g_k);
    cudaGetSymbolAddress((void**)&v,  g_v);
    cudaGetSymbolAddress((void**)&o,  g_o);
    cudaGetSymbolAddress((void**)&a3, g_a3);
    cudaGetSymbolAddress((void**)&w3, g_w3);
    const size_t WSZ = (size_t)GN * KEXP;

    cudaFuncSetAttribute((const void*)attn_kernel,
                         cudaFuncAttributeMaxDynamicSharedMemorySize, ATT_SMEM_BYTES);

    dim3 blk(256);
    dim3 gW(512 * 512 / 256);
    dim3 gAct((unsigned)((size_t)GM * 128 / 256));
    dim3 gQKV(GN / BN, GM / BM, 3);     // (4, 384, 3)
    dim3 gFC(GN / BN, GM / BM, 1);      // (4, 384)
    dim3 gAtt(BT * KH, Nc / 64);        // (768, 8)

    // weight splits
    conv_w<<<gW, blk>>>(Wq, w3 + 0 * WSZ);
    conv_w<<<gW, blk>>>(Wk, w3 + 1 * WSZ);
    conv_w<<<gW, blk>>>(Wv, w3 + 2 * WSZ);
    conv_w<<<gW, blk>>>(W1, w3 + 3 * WSZ);
    conv_w<<<gW, blk>>>(W2, w3 + 4 * WSZ);

    // 1) split X, fused QKV GEMM
    conv_act<<<gAct, blk>>>(X, a3);
    gemm_mma<true><<<gQKV, blk>>>(a3, w3, w3 + WSZ, w3 + 2 * WSZ,
                                  bq, bk, bv, q, k, v);
    // 2) attention
    attn_kernel<<<gAtt, blk, ATT_SMEM_BYTES>>>(q, k, v, o);
    // 3) FC1 (h reuses g_q; it is free after attention)
    conv_act<<<gAct, blk>>>(o, a3);
    gemm_mma<true><<<gFC, blk>>>(a3, w3 + 3 * WSZ, w3 + 3 * WSZ, w3 + 3 * WSZ,
                                 b1, b1, b1, q, q, q);
    // 4) FC2 -> out
    conv_act<<<gAct, blk>>>(q, a3);
    gemm_mma<false><<<gFC, blk>>>(a3, w3 + 4 * WSZ, w3 + 4 * WSZ, w3 + 4 * WSZ,
                                  b2, b2, b2, out, out, out);
}

// round 4
// speedup vs baseline: 2.4555x; 1.5685x over previous
#include <cuda_runtime.h>
#include <cuda_bf16.h>
#include <cstdint>

// ---------------------------------------------------------------------------
// Problem constants
// ---------------------------------------------------------------------------
constexpr int Bc = 8, Tc = 12, Nc = 512, Dc = 512;
constexpr int BT = Bc * Tc;                 // 96
constexpr int GM = BT * Nc;                 // 49152 rows
constexpr int GN = 512;                     // output dim
constexpr int KH = 8;                       // heads
constexpr int KEXP = 3 * 512;               // 1536 split-expanded K

// Scratch (allocation-free rule: __device__ globals)
__device__ __nv_bfloat16  g_a3a[(size_t)GM * KEXP];
__device__ __nv_bfloat16  g_a3b[(size_t)GM * KEXP];
__device__ __nv_bfloat16  g_w3[5 * (size_t)GN * KEXP];
__device__ __nv_bfloat16  g_qh[(size_t)GM * 512];
__device__ __nv_bfloat16  g_ql[(size_t)GM * 512];
__device__ __nv_bfloat16  g_kh[(size_t)GM * 512];
__device__ __nv_bfloat16  g_kl[(size_t)GM * 512];
__device__ __nv_bfloat16  g_vh[(size_t)GM * 512];
__device__ __nv_bfloat16  g_vl[(size_t)GM * 512];

__device__ __forceinline__ uint32_t smem_to_u32(const void* p) {
    uint32_t a;
    asm("{ .reg .u64 t; cvta.to.shared.u64 t, %1; cvt.u32.u64 %0, t; }" : "=r"(a) : "l"(p));
    return a;
}

// ---------------------------------------------------------------------------
// Portable tensor-core primitives (sm_80+ ISA)
// ---------------------------------------------------------------------------
__device__ __forceinline__ void ldsm_x4(uint32_t& r0, uint32_t& r1, uint32_t& r2, uint32_t& r3,
                                        uint32_t addr) {
    asm volatile("ldmatrix.sync.aligned.m8n8.x4.shared.b16 {%0,%1,%2,%3}, [%4];"
                 : "=r"(r0), "=r"(r1), "=r"(r2), "=r"(r3) : "r"(addr));
}
__device__ __forceinline__ void ldsm_x4_t(uint32_t& r0, uint32_t& r1, uint32_t& r2, uint32_t& r3,
                                          uint32_t addr) {
    asm volatile("ldmatrix.sync.aligned.m8n8.x4.trans.shared.b16 {%0,%1,%2,%3}, [%4];"
                 : "=r"(r0), "=r"(r1), "=r"(r2), "=r"(r3) : "r"(addr));
}
__device__ __forceinline__ void mma16816(float* d, const uint32_t* a, const uint32_t* b) {
    asm volatile("mma.sync.aligned.m16n8k16.row.col.f32.bf16.bf16.f32 "
                 "{%0,%1,%2,%3}, {%4,%5,%6,%7}, {%8,%9}, {%0,%1,%2,%3};"
                 : "+f"(d[0]), "+f"(d[1]), "+f"(d[2]), "+f"(d[3])
                 : "r"(a[0]), "r"(a[1]), "r"(a[2]), "r"(a[3]), "r"(b[0]), "r"(b[1]));
}
__device__ __forceinline__ void cp_async16(uint32_t smem_addr, const void* gptr) {
    asm volatile("cp.async.cg.shared.global [%0], [%1], 16;" :: "r"(smem_addr), "l"(gptr));
}
#define CP_COMMIT() asm volatile("cp.async.commit_group;" ::: "memory")
#define CP_WAIT(n)  asm volatile("cp.async.wait_group %0;" :: "n"(n) : "memory")

__device__ __forceinline__ uint32_t pack_bf16x2(float lo, float hi) {
    uint32_t r;
    asm("cvt.rn.bf16x2.f32 %0, %1, %2;" : "=r"(r) : "f"(hi), "f"(lo));
    return r;
}

// split helpers -------------------------------------------------------------
__device__ __forceinline__ void split_bf16(float x, __nv_bfloat16& h, __nv_bfloat16& l) {
    h = __float2bfloat16_rn(x);
    l = __float2bfloat16_rn(x - __bfloat162float(h));
}
__device__ __forceinline__ void store_split_pair(__nv_bfloat16* H, __nv_bfloat16* L,
                                                 size_t idx, float v0, float v1) {
    __nv_bfloat162 h2, l2;
    split_bf16(v0, h2.x, l2.x);
    split_bf16(v1, h2.y, l2.y);
    *(__nv_bfloat162*)(H + idx) = h2;
    *(__nv_bfloat162*)(L + idx) = l2;
}
__device__ __forceinline__ void store_a3_pair(__nv_bfloat16* A3, size_t row, int col,
                                              float v0, float v1) {
    __nv_bfloat162 h2, l2;
    split_bf16(v0, h2.x, l2.x);
    split_bf16(v1, h2.y, l2.y);
    __nv_bfloat16* p = A3 + row * KEXP + col;
    *(__nv_bfloat162*)(p)        = h2;
    *(__nv_bfloat162*)(p + 512)  = l2;
    *(__nv_bfloat162*)(p + 1024) = h2;
}

// ---------------------------------------------------------------------------
// Conversion kernels (X and weights only; all other conversions fused)
// ---------------------------------------------------------------------------
__global__ __launch_bounds__(256) void conv_act(const float* __restrict__ A,
                                                __nv_bfloat16* __restrict__ A3) {
    size_t i = (size_t)blockIdx.x * 256 + threadIdx.x;   // over GM*128
    size_t row = i >> 7;
    int c4 = (int)(i & 127) << 2;
    float4 a = *(const float4*)(A + (row << 9) + c4);
    __nv_bfloat16 h[4], l[4];
    split_bf16(a.x, h[0], l[0]); split_bf16(a.y, h[1], l[1]);
    split_bf16(a.z, h[2], l[2]); split_bf16(a.w, h[3], l[3]);
    __nv_bfloat16* dst = A3 + row * KEXP + c4;
    *(uint2*)(dst)        = *(uint2*)h;
    *(uint2*)(dst + 512)  = *(uint2*)l;
    *(uint2*)(dst + 1024) = *(uint2*)h;
}

__global__ __launch_bounds__(256) void conv_w(const float* __restrict__ W,
                                              __nv_bfloat16* __restrict__ W3T) {
    int i = blockIdx.x * 256 + threadIdx.x;   // 512*512
    int k = i >> 9, n = i & 511;
    __nv_bfloat16 h, l;
    split_bf16(W[i], h, l);
    __nv_bfloat16* dst = W3T + (size_t)n * KEXP + k;
    dst[0]    = h;
    dst[512]  = h;
    dst[1024] = l;
}

// ---------------------------------------------------------------------------
// HMMA GEMM: C[M,N] = act(A3[M,1536] @ W3T[N,1536]^T + bias)
// MODE 0: fp32 out.  MODE 1: split h/l bf16.  MODE 2: A3 [h|l|h] layout.
// ---------------------------------------------------------------------------
constexpr int BM = 128, BN = 128, BK = 32;
constexpr int KST = 40;
constexpr int NIT = KEXP / BK;               // 48

template <bool RELU, int MODE>
__global__ __launch_bounds__(256)
void gemm_mma(const __nv_bfloat16* __restrict__ A3,
              const __nv_bfloat16* __restrict__ B0, const __nv_bfloat16* __restrict__ B1,
              const __nv_bfloat16* __restrict__ B2,
              const float* __restrict__ bias0, const float* __restrict__ bias1,
              const float* __restrict__ bias2,
              float* __restrict__ F0,
              __nv_bfloat16* __restrict__ H0, __nv_bfloat16* __restrict__ L0,
              __nv_bfloat16* __restrict__ H1, __nv_bfloat16* __restrict__ L1,
              __nv_bfloat16* __restrict__ H2, __nv_bfloat16* __restrict__ L2,
              __nv_bfloat16* __restrict__ A3out)
{
    const int z = blockIdx.z;
    const __nv_bfloat16* Bw = (z == 0) ? B0 : (z == 1) ? B1 : B2;
    const float* bias       = (z == 0) ? bias0 : (z == 1) ? bias1 : bias2;
    __nv_bfloat16* Ho       = (z == 0) ? H0 : (z == 1) ? H1 : H2;
    __nv_bfloat16* Lo       = (z == 0) ? L0 : (z == 1) ? L1 : L2;

    __shared__ __nv_bfloat16 sA[2][BM * KST];
    __shared__ __nv_bfloat16 sB[2][BN * KST];

    const int tid = threadIdx.x;
    const int wid = tid >> 5;
    const int lid = tid & 31;
    const int m0 = (wid >> 2) * 64;
    const int n0 = (wid & 3) * 32;

    const size_t mBase = (size_t)blockIdx.y * BM;
    const size_t nBase = (size_t)blockIdx.x * BN;
    const __nv_bfloat16* Ag = A3 + mBase * KEXP;
    const __nv_bfloat16* Bg = Bw + nBase * KEXP;

    const uint32_t sAu = smem_to_u32(sA);
    const uint32_t sBu = smem_to_u32(sB);

    const int ldr = tid >> 2;
    const int ldu = (tid & 3) * 8;

    auto load_stage = [&](int buf, int it) {
        const int k0 = it * BK;
#pragma unroll
        for (int p = 0; p < 2; p++) {
            int r = ldr + p * 64;
            uint32_t soff = (uint32_t)((r * KST + ldu) * 2);
            cp_async16(sAu + (uint32_t)(buf * BM * KST * 2) + soff, Ag + (size_t)r * KEXP + k0 + ldu);
            cp_async16(sBu + (uint32_t)(buf * BN * KST * 2) + soff, Bg + (size_t)r * KEXP + k0 + ldu);
        }
        CP_COMMIT();
    };

    float acc[4][4][4];
#pragma unroll
    for (int i = 0; i < 4; i++)
#pragma unroll
        for (int j = 0; j < 4; j++)
#pragma unroll
            for (int c = 0; c < 4; c++) acc[i][j][c] = 0.0f;

    const int seg = lid >> 3, lrow = lid & 7;
    const int a_roff = lrow + ((seg & 1) << 3);
    const int a_coff = (seg >> 1) << 3;
    const int b_roff = lrow + ((seg >> 1) << 3);
    const int b_coff = (seg & 1) << 3;

    load_stage(0, 0);

    for (int it = 0; it < NIT; ++it) {
        const int buf = it & 1;
        if (it + 1 < NIT) {
            load_stage(buf ^ 1, it + 1);
            CP_WAIT(1);
        } else {
            CP_WAIT(0);
        }
        __syncthreads();

        const uint32_t aB = sAu + (uint32_t)(buf * BM * KST * 2);
        const uint32_t bB = sBu + (uint32_t)(buf * BN * KST * 2);

#pragma unroll
        for (int kk = 0; kk < 2; kk++) {
            uint32_t ra[4][4], rb[2][4];
#pragma unroll
            for (int mi = 0; mi < 4; mi++) {
                uint32_t addr = aB + (uint32_t)(((m0 + mi * 16 + a_roff) * KST + kk * 16 + a_coff) * 2);
                ldsm_x4(ra[mi][0], ra[mi][1], ra[mi][2], ra[mi][3], addr);
            }
#pragma unroll
            for (int nj = 0; nj < 2; nj++) {
                uint32_t addr = bB + (uint32_t)(((n0 + nj * 16 + b_roff) * KST + kk * 16 + b_coff) * 2);
                ldsm_x4(rb[nj][0], rb[nj][1], rb[nj][2], rb[nj][3], addr);
            }
#pragma unroll
            for (int mi = 0; mi < 4; mi++)
#pragma unroll
                for (int nj = 0; nj < 4; nj++)
                    mma16816(acc[mi][nj], ra[mi], &rb[nj >> 1][(nj & 1) * 2]);
        }
        __syncthreads();
    }

    // epilogue
    const int gr = lid >> 2;
    const int gc = (lid & 3) * 2;
#pragma unroll
    for (int mi = 0; mi < 4; mi++) {
        const size_t row0 = mBase + m0 + mi * 16 + gr;
#pragma unroll
        for (int nj = 0; nj < 4; nj++) {
            const int col = (int)nBase + n0 + nj * 8 + gc;
            const float bx = __ldg(&bias[col]);
            const float by = __ldg(&bias[col + 1]);
            float v0 = acc[mi][nj][0] + bx;
            float v1 = acc[mi][nj][1] + by;
            float v2 = acc[mi][nj][2] + bx;
            float v3 = acc[mi][nj][3] + by;
            if (RELU) {
                v0 = fmaxf(v0, 0.f); v1 = fmaxf(v1, 0.f);
                v2 = fmaxf(v2, 0.f); v3 = fmaxf(v3, 0.f);
            }
            if (MODE == 0) {
                *(float2*)(F0 + row0 * GN + col)       = make_float2(v0, v1);
                *(float2*)(F0 + (row0 + 8) * GN + col) = make_float2(v2, v3);
            } else if (MODE == 1) {
                store_split_pair(Ho, Lo, row0 * GN + col, v0, v1);
                store_split_pair(Ho, Lo, (row0 + 8) * GN + col, v2, v3);
            } else {
                store_a3_pair(A3out, row0, col, v0, v1);
                store_a3_pair(A3out, row0 + 8, col, v2, v3);
            }
        }
    }
}

// ---------------------------------------------------------------------------
// HMMA flash attention: CTA = 128 queries of one head.
// S = qh*kh + ql*kh + qh*kl (split), P=exp(S/8) in fp32, no max-sub (logits
// small, all inputs >=0). P reused in-register as A fragment for P*V.
// Output written directly in A3 [h|l|h] layout for FC1.
// ---------------------------------------------------------------------------
constexpr int AST = 72;                       // smem row stride (bf16)
constexpr int SQH = 0;
constexpr int SQL = 128 * AST;                // elems
constexpr int SKV0 = 2 * 128 * AST;
constexpr int STG = 3 * 64 * AST;             // per-stage elems (kh, kl, v)
constexpr int ATT_DSMEM = (SKV0 + 2 * STG) * 2;  // 92160 bytes

__global__ __launch_bounds__(256)
void attn_mma(const __nv_bfloat16* __restrict__ qh, const __nv_bfloat16* __restrict__ ql,
              const __nv_bfloat16* __restrict__ kh, const __nv_bfloat16* __restrict__ kl,
              const __nv_bfloat16* __restrict__ vh, __nv_bfloat16* __restrict__ a3out)
{
    extern __shared__ __nv_bfloat16 smb[];
    const uint32_t sb = smem_to_u32(smb);

    const int tid = threadIdx.x;
    const int wid = tid >> 5;
    const int lid = tid & 31;
    const int m0 = wid * 16;

    const int head = blockIdx.x;
    const int bt = head >> 3;
    const int hk = head & 7;
    const size_t qrow0 = (size_t)bt * 512 + blockIdx.y * 128;
    const size_t krow0 = (size_t)bt * 512;
    const int colb = hk * 64;

    const int seg = lid >> 3, lrow = lid & 7;
    const int a_roff = lrow + ((seg & 1) << 3);
    const int a_coff = (seg >> 1) << 3;
    const int b_roff = lrow + ((seg >> 1) << 3);
    const int b_coff = (seg & 1) << 3;
    // V (trans) lane offsets: rows=key, cols=dd
    const int v_roff = lrow + ((seg & 1) << 3);
    const int v_coff = (seg >> 1) << 3;

    // ---- stage Q (group 0) ----
    {
#pragma unroll
        for (int t = 0; t < 4; t++) {
            int c = tid + t * 256;              // 1024 chunks per array
            int r = c >> 3, u = (c & 7) * 8;
            cp_async16(sb + (uint32_t)((SQH + r * AST + u) * 2),
                       qh + (qrow0 + r) * 512 + colb + u);
            cp_async16(sb + (uint32_t)((SQL + r * AST + u) * 2),
                       ql + (qrow0 + r) * 512 + colb + u);
        }
        CP_COMMIT();
    }
    // ---- stage KV helper ----
    auto stage_kv = [&](int kt, int buf) {
        const size_t kr = krow0 + kt * 64;
        const uint32_t b = SKV0 + buf * STG;
#pragma unroll
        for (int t = 0; t < 2; t++) {
            int c = tid + t * 256;              // 512 chunks per array
            int r = c >> 3, u = (c & 7) * 8;
            cp_async16(sb + (uint32_t)((b + r * AST + u) * 2),
                       kh + (kr + r) * 512 + colb + u);
            cp_async16(sb + (uint32_t)((b + 64 * AST + r * AST + u) * 2),
                       kl + (kr + r) * 512 + colb + u);
            cp_async16(sb + (uint32_t)((b + 128 * AST + r * AST + u) * 2),
                       vh + (kr + r) * 512 + colb + u);
        }
        CP_COMMIT();
    };

    stage_kv(0, 0);
    CP_WAIT(1);          // Q complete
    __syncthreads();

    // ---- Q fragments ----
    uint32_t qfh[4][4], qfl[4][4];
#pragma unroll
    for (int ks = 0; ks < 4; ks++) {
        ldsm_x4(qfh[ks][0], qfh[ks][1], qfh[ks][2], qfh[ks][3],
                sb + (uint32_t)(((SQH + (m0 + a_roff) * AST) + ks * 16 + a_coff) * 2));
        ldsm_x4(qfl[ks][0], qfl[ks][1], qfl[ks][2], qfl[ks][3],
                sb + (uint32_t)(((SQL + (m0 + a_roff) * AST) + ks * 16 + a_coff) * 2));
    }

    float oacc[8][4];
#pragma unroll
    for (int j = 0; j < 8; j++)
#pragma unroll
        for (int c = 0; c < 4; c++) oacc[j][c] = 0.0f;
    float rs0 = 0.f, rs1 = 0.f;

    for (int kt = 0; kt < 8; kt++) {
        if (kt + 1 < 8) {
            stage_kv(kt + 1, (kt + 1) & 1);
            CP_WAIT(1);
        } else {
            CP_WAIT(0);
        }
        __syncthreads();

        const uint32_t base = SKV0 + (kt & 1) * STG;

        // --- S = Q K^T (split) ---
        float sacc[8][4];
#pragma unroll
        for (int j = 0; j < 8; j++)
#pragma unroll
            for (int c = 0; c < 4; c++) sacc[j][c] = 0.0f;

#pragma unroll
        for (int ks = 0; ks < 4; ks++) {
            uint32_t kbh[4][4], kbl[4][4];
#pragma unroll
            for (int j = 0; j < 4; j++) {
                ldsm_x4(kbh[j][0], kbh[j][1], kbh[j][2], kbh[j][3],
                        sb + (uint32_t)(((base + (j * 16 + b_roff) * AST) + ks * 16 + b_coff) * 2));
                ldsm_x4(kbl[j][0], kbl[j][1], kbl[j][2], kbl[j][3],
                        sb + (uint32_t)(((base + 64 * AST + (j * 16 + b_roff) * AST) + ks * 16 + b_coff) * 2));
            }
#pragma unroll
            for (int j = 0; j < 4; j++) {
                mma16816(sacc[2 * j],     qfh[ks], &kbh[j][0]);
                mma16816(sacc[2 * j + 1], qfh[ks], &kbh[j][2]);
                mma16816(sacc[2 * j],     qfl[ks], &kbh[j][0]);
                mma16816(sacc[2 * j + 1], qfl[ks], &kbh[j][2]);
                mma16816(sacc[2 * j],     qfh[ks], &kbl[j][0]);
                mma16816(sacc[2 * j + 1], qfh[ks], &kbl[j][2]);
            }
        }

        // --- P = exp(S/8), rowsums ---
#pragma unroll
        for (int j = 0; j < 8; j++) {
            sacc[j][0] = __expf(sacc[j][0] * 0.125f);
            sacc[j][1] = __expf(sacc[j][1] * 0.125f);
            sacc[j][2] = __expf(sacc[j][2] * 0.125f);
            sacc[j][3] = __expf(sacc[j][3] * 0.125f);
            rs0 += sacc[j][0] + sacc[j][1];
            rs1 += sacc[j][2] + sacc[j][3];
        }

        // --- O += P V ---
#pragma unroll
        for (int pk = 0; pk < 4; pk++) {
            uint32_t pa[4];
            pa[0] = pack_bf16x2(sacc[2 * pk][0],     sacc[2 * pk][1]);
            pa[1] = pack_bf16x2(sacc[2 * pk][2],     sacc[2 * pk][3]);
            pa[2] = pack_bf16x2(sacc[2 * pk + 1][0], sacc[2 * pk + 1][1]);
            pa[3] = pack_bf16x2(sacc[2 * pk + 1][2], sacc[2 * pk + 1][3]);
            uint32_t vb[4][4];
#pragma unroll
            for (int dj = 0; dj < 4; dj++)
                ldsm_x4_t(vb[dj][0], vb[dj][1], vb[dj][2], vb[dj][3],
                          sb + (uint32_t)(((base + 128 * AST + (pk * 16 + v_roff) * AST) + dj * 16 + v_coff) * 2));
#pragma unroll
            for (int dj = 0; dj < 4; dj++) {
                mma16816(oacc[2 * dj],     pa, &vb[dj][0]);
                mma16816(oacc[2 * dj + 1], pa, &vb[dj][2]);
            }
        }
        __syncthreads();
    }

    // --- row-sum reduce across the 4 lanes of each row group ---
    rs0 += __shfl_xor_sync(0xFFFFFFFFu, rs0, 1);
    rs0 += __shfl_xor_sync(0xFFFFFFFFu, rs0, 2);
    rs1 += __shfl_xor_sync(0xFFFFFFFFu, rs1, 1);
    rs1 += __shfl_xor_sync(0xFFFFFFFFu, rs1, 2);
    const float rinv0 = 1.0f / rs0;
    const float rinv1 = 1.0f / rs1;

    // --- normalize + write A3 [h|l|h] ---
    const int gr = lid >> 2;
    const int gc = (lid & 3) * 2;
    const size_t row0 = qrow0 + m0 + gr;
#pragma unroll
    for (int nj = 0; nj < 8; nj++) {
        const int col = colb + nj * 8 + gc;
        store_a3_pair(a3out, row0,     col, oacc[nj][0] * rinv0, oacc[nj][1] * rinv0);
        store_a3_pair(a3out, row0 + 8, col, oacc[nj][2] * rinv1, oacc[nj][3] * rinv1);
    }
}

// ---------------------------------------------------------------------------
// Launch
// ---------------------------------------------------------------------------
extern "C" void kernel_launch(void* const* d_in, const int* in_sizes, int n_in,
                              void* d_out, int out_size)
{
    (void)in_sizes; (void)n_in; (void)out_size;
    const float* X  = (const float*)d_in[0];
    const float* Wq = (const float*)d_in[2];
    const float* bq = (const float*)d_in[3];
    const float* Wk = (const float*)d_in[4];
    const float* bk = (const float*)d_in[5];
    const float* Wv = (const float*)d_in[6];
    const float* bv = (const float*)d_in[7];
    const float* W1 = (const float*)d_in[8];
    const float* b1 = (const float*)d_in[9];
    const float* W2 = (const float*)d_in[10];
    const float* b2 = (const float*)d_in[11];
    float* out = (float*)d_out;

    __nv_bfloat16 *a3a, *a3b, *w3, *qh, *ql, *kh, *kl, *vh, *vl;
    cudaGetSymbolAddress((void**)&a3a, g_a3a);
    cudaGetSymbolAddress((void**)&a3b, g_a3b);
    cudaGetSymbolAddress((void**)&w3,  g_w3);
    cudaGetSymbolAddress((void**)&qh,  g_qh);
    cudaGetSymbolAddress((void**)&ql,  g_ql);
    cudaGetSymbolAddress((void**)&kh,  g_kh);
    cudaGetSymbolAddress((void**)&kl,  g_kl);
    cudaGetSymbolAddress((void**)&vh,  g_vh);
    cudaGetSymbolAddress((void**)&vl,  g_vl);
    const size_t WSZ = (size_t)GN * KEXP;

    cudaFuncSetAttribute((const void*)attn_mma,
                         cudaFuncAttributeMaxDynamicSharedMemorySize, ATT_DSMEM);

    dim3 blk(256);
    dim3 gW(512 * 512 / 256);
    dim3 gAct((unsigned)((size_t)GM * 128 / 256));
    dim3 gQKV(GN / BN, GM / BM, 3);
    dim3 gFC(GN / BN, GM / BM, 1);
    dim3 gAtt(BT * KH, 4);

    conv_w<<<gW, blk>>>(Wq, w3 + 0 * WSZ);
    conv_w<<<gW, blk>>>(Wk, w3 + 1 * WSZ);
    conv_w<<<gW, blk>>>(Wv, w3 + 2 * WSZ);
    conv_w<<<gW, blk>>>(W1, w3 + 3 * WSZ);
    conv_w<<<gW, blk>>>(W2, w3 + 4 * WSZ);

    // 1) split X -> a3a; QKV GEMM -> split q/k/v
    conv_act<<<gAct, blk>>>(X, a3a);
    gemm_mma<true, 1><<<gQKV, blk>>>(a3a, w3, w3 + WSZ, w3 + 2 * WSZ,
                                     bq, bk, bv, nullptr,
                                     qh, ql, kh, kl, vh, vl, nullptr);
    // 2) attention -> a3b (A3 layout, fused)
    attn_mma<<<gAtt, blk, ATT_DSMEM>>>(qh, ql, kh, kl, vh, a3b);
    // 3) FC1 -> a3a (A3 layout, fused, ReLU)
    gemm_mma<true, 2><<<gFC, blk>>>(a3b, w3 + 3 * WSZ, w3 + 3 * WSZ, w3 + 3 * WSZ,
                                    b1, b1, b1, nullptr,
                                    nullptr, nullptr, nullptr, nullptr, nullptr, nullptr, a3a);
    // 4) FC2 -> out (fp32)
    gemm_mma<false, 0><<<gFC, blk>>>(a3a, w3 + 4 * WSZ, w3 + 4 * WSZ, w3 + 4 * WSZ,
                                     b2, b2, b2, out,
                                     nullptr, nullptr, nullptr, nullptr, nullptr, nullptr, nullptr);
}

// round 5
// speedup vs baseline: 3.9867x; 1.6236x over previous
#include <cuda_runtime.h>
#include <cuda_fp16.h>
#include <cstdint>

// ---------------------------------------------------------------------------
// Problem constants
// ---------------------------------------------------------------------------
constexpr int Bc = 8, Tc = 12, Nc = 512;
constexpr int BT = Bc * Tc;                 // 96
constexpr int GM = BT * Nc;                 // 49152 rows
constexpr int GN = 512;                     // output dim
constexpr int KH = 8;                       // heads
constexpr int KA = 1024;                    // [Ah|Al] expanded activation width

// Scratch (allocation-free rule: __device__ globals)
__device__ __half g_a2a[(size_t)GM * KA];
__device__ __half g_a2b[(size_t)GM * KA];
__device__ __half g_w2[5 * (size_t)GN * 512];   // fp16 weights, [n][k]
__device__ __half g_qh[(size_t)GM * 512];
__device__ __half g_ql[(size_t)GM * 512];
__device__ __half g_kh[(size_t)GM * 512];
__device__ __half g_vh[(size_t)GM * 512];

__device__ __forceinline__ uint32_t smem_to_u32(const void* p) {
    uint32_t a;
    asm("{ .reg .u64 t; cvta.to.shared.u64 t, %1; cvt.u32.u64 %0, t; }" : "=r"(a) : "l"(p));
    return a;
}

// ---------------------------------------------------------------------------
// Portable tensor-core primitives (sm_80+ ISA)
// ---------------------------------------------------------------------------
__device__ __forceinline__ void ldsm_x4(uint32_t& r0, uint32_t& r1, uint32_t& r2, uint32_t& r3,
                                        uint32_t addr) {
    asm volatile("ldmatrix.sync.aligned.m8n8.x4.shared.b16 {%0,%1,%2,%3}, [%4];"
                 : "=r"(r0), "=r"(r1), "=r"(r2), "=r"(r3) : "r"(addr));
}
__device__ __forceinline__ void ldsm_x4_t(uint32_t& r0, uint32_t& r1, uint32_t& r2, uint32_t& r3,
                                          uint32_t addr) {
    asm volatile("ldmatrix.sync.aligned.m8n8.x4.trans.shared.b16 {%0,%1,%2,%3}, [%4];"
                 : "=r"(r0), "=r"(r1), "=r"(r2), "=r"(r3) : "r"(addr));
}
__device__ __forceinline__ void mma16816(float* d, const uint32_t* a, const uint32_t* b) {
    asm volatile("mma.sync.aligned.m16n8k16.row.col.f32.f16.f16.f32 "
                 "{%0,%1,%2,%3}, {%4,%5,%6,%7}, {%8,%9}, {%0,%1,%2,%3};"
                 : "+f"(d[0]), "+f"(d[1]), "+f"(d[2]), "+f"(d[3])
                 : "r"(a[0]), "r"(a[1]), "r"(a[2]), "r"(a[3]), "r"(b[0]), "r"(b[1]));
}
__device__ __forceinline__ void cp_async16(uint32_t smem_addr, const void* gptr) {
    asm volatile("cp.async.cg.shared.global [%0], [%1], 16;" :: "r"(smem_addr), "l"(gptr));
}
#define CP_COMMIT() asm volatile("cp.async.commit_group;" ::: "memory")
#define CP_WAIT(n)  asm volatile("cp.async.wait_group %0;" :: "n"(n) : "memory")

__device__ __forceinline__ uint32_t pack_f16x2(float lo, float hi) {
    uint32_t r;
    asm("cvt.rn.f16x2.f32 %0, %1, %2;" : "=r"(r) : "f"(hi), "f"(lo));
    return r;
}

// split helpers -------------------------------------------------------------
__device__ __forceinline__ void split_f16(float x, __half& h, __half& l) {
    h = __float2half_rn(x);
    l = __float2half_rn(x - __half2float(h));
}
// store split pair into separate H/L arrays (L optional)
__device__ __forceinline__ void store_split_pair(__half* H, __half* L,
                                                 size_t idx, float v0, float v1) {
    __half2 h2, l2;
    split_f16(v0, h2.x, l2.x);
    split_f16(v1, h2.y, l2.y);
    *(__half2*)(H + idx) = h2;
    if (L) *(__half2*)(L + idx) = l2;
}
// store into [Ah|Al] A2 layout (row stride KA)
__device__ __forceinline__ void store_a2_pair(__half* A2, size_t row, int col,
                                              float v0, float v1) {
    __half2 h2, l2;
    split_f16(v0, h2.x, l2.x);
    split_f16(v1, h2.y, l2.y);
    __half* p = A2 + row * KA + col;
    *(__half2*)(p)       = h2;
    *(__half2*)(p + 512) = l2;
}

// ---------------------------------------------------------------------------
// Conversion kernels (X and weights only; all other conversions fused)
// ---------------------------------------------------------------------------
__global__ __launch_bounds__(256) void conv_act(const float* __restrict__ A,
                                                __half* __restrict__ A2) {
    size_t i = (size_t)blockIdx.x * 256 + threadIdx.x;   // over GM*128
    size_t row = i >> 7;
    int c4 = (int)(i & 127) << 2;
    float4 a = *(const float4*)(A + (row << 9) + c4);
    __half h[4], l[4];
    split_f16(a.x, h[0], l[0]); split_f16(a.y, h[1], l[1]);
    split_f16(a.z, h[2], l[2]); split_f16(a.w, h[3], l[3]);
    __half* dst = A2 + row * KA + c4;
    *(uint2*)(dst)       = *(uint2*)h;
    *(uint2*)(dst + 512) = *(uint2*)l;
}

// W[512k][512n] fp32 -> Wh fp16 [n][k]
__global__ __launch_bounds__(256) void conv_w(const float* __restrict__ W,
                                              __half* __restrict__ W2T) {
    int i = blockIdx.x * 256 + threadIdx.x;   // 512*512
    int k = i >> 9, n = i & 511;
    W2T[(size_t)n * 512 + k] = __float2half_rn(W[i]);
}

// ---------------------------------------------------------------------------
// HMMA GEMM: C[M,N] = act(A2[M,1024] @ Wh[N,512]^T + bias)
//   (B k-index wraps mod 512: second A half multiplies the same Wh)
// MODE 0: fp32 out.  MODE 1: split h/l arrays.  MODE 2: A2 [h|l] layout.
// CTA 128x128, BK=64, 8 warps (2x4), warp 64x32, 2-stage cp.async, dyn smem.
// ---------------------------------------------------------------------------
constexpr int BM = 128, BN = 128, BK = 64;
constexpr int KST = 72;                       // padded smem stride (fp16 elems)
constexpr int NIT = KA / BK;                  // 16
constexpr int STG_ELEMS = (BM + BN) * KST;    // per-stage elems
constexpr int GEMM_DSMEM = 2 * STG_ELEMS * 2; // 73728 bytes

template <bool RELU, int MODE>
__global__ __launch_bounds__(256)
void gemm_mma(const __half* __restrict__ A2,
              const __half* __restrict__ B0, const __half* __restrict__ B1,
              const __half* __restrict__ B2,
              const float* __restrict__ bias0, const float* __restrict__ bias1,
              const float* __restrict__ bias2,
              float* __restrict__ F0,
              __half* __restrict__ H0, __half* __restrict__ L0,
              __half* __restrict__ H1, __half* __restrict__ H2,
              __half* __restrict__ A2out)
{
    const int z = blockIdx.z;
    const __half* Bw  = (z == 0) ? B0 : (z == 1) ? B1 : B2;
    const float* bias = (z == 0) ? bias0 : (z == 1) ? bias1 : bias2;
    __half* Ho        = (z == 0) ? H0 : (z == 1) ? H1 : H2;
    __half* Lo        = (z == 0) ? L0 : nullptr;

    extern __shared__ __align__(16) __half dynsm[];
    const uint32_t sbase = smem_to_u32(dynsm);

    const int tid = threadIdx.x;
    const int wid = tid >> 5;
    const int lid = tid & 31;
    const int m0 = (wid >> 2) * 64;
    const int n0 = (wid & 3) * 32;

    const size_t mBase = (size_t)blockIdx.y * BM;
    const size_t nBase = (size_t)blockIdx.x * BN;
    const __half* Ag = A2 + mBase * KA;
    const __half* Bg = Bw + nBase * 512;

    auto load_stage = [&](int buf, int it) {
        const int k0 = it * BK;
        const int kb = k0 & 511;
        const uint32_t aOff = sbase + (uint32_t)(buf * STG_ELEMS) * 2;
        const uint32_t bOff = aOff + (uint32_t)(BM * KST) * 2;
#pragma unroll
        for (int p = 0; p < 4; p++) {
            int idx = tid + p * 256;            // 0..1023
            int r = idx >> 3, u = (idx & 7) * 8;
            uint32_t soff = (uint32_t)((r * KST + u) * 2);
            cp_async16(aOff + soff, Ag + (size_t)r * KA + k0 + u);
            cp_async16(bOff + soff, Bg + (size_t)r * 512 + kb + u);
        }
        CP_COMMIT();
    };

    float acc[4][4][4];
#pragma unroll
    for (int i = 0; i < 4; i++)
#pragma unroll
        for (int j = 0; j < 4; j++)
#pragma unroll
            for (int c = 0; c < 4; c++) acc[i][j][c] = 0.0f;

    const int seg = lid >> 3, lrow = lid & 7;
    const int a_roff = lrow + ((seg & 1) << 3);
    const int a_coff = (seg >> 1) << 3;
    const int b_roff = lrow + ((seg >> 1) << 3);
    const int b_coff = (seg & 1) << 3;

    load_stage(0, 0);

    for (int it = 0; it < NIT; ++it) {
        const int buf = it & 1;
        if (it + 1 < NIT) {
            load_stage(buf ^ 1, it + 1);
            CP_WAIT(1);
        } else {
            CP_WAIT(0);
        }
        __syncthreads();

        const uint32_t aB = sbase + (uint32_t)(buf * STG_ELEMS) * 2;
        const uint32_t bB = aB + (uint32_t)(BM * KST) * 2;

#pragma unroll
        for (int kk = 0; kk < 4; kk++) {
            uint32_t ra[4][4], rb[2][4];
#pragma unroll
            for (int mi = 0; mi < 4; mi++) {
                uint32_t addr = aB + (uint32_t)(((m0 + mi * 16 + a_roff) * KST + kk * 16 + a_coff) * 2);
                ldsm_x4(ra[mi][0], ra[mi][1], ra[mi][2], ra[mi][3], addr);
            }
#pragma unroll
            for (int nj = 0; nj < 2; nj++) {
                uint32_t addr = bB + (uint32_t)(((n0 + nj * 16 + b_roff) * KST + kk * 16 + b_coff) * 2);
                ldsm_x4(rb[nj][0], rb[nj][1], rb[nj][2], rb[nj][3], addr);
            }
#pragma unroll
            for (int mi = 0; mi < 4; mi++)
#pragma unroll
                for (int nj = 0; nj < 4; nj++)
                    mma16816(acc[mi][nj], ra[mi], &rb[nj >> 1][(nj & 1) * 2]);
        }
        __syncthreads();
    }

    // epilogue
    const int gr = lid >> 2;
    const int gc = (lid & 3) * 2;
#pragma unroll
    for (int mi = 0; mi < 4; mi++) {
        const size_t row0 = mBase + m0 + mi * 16 + gr;
#pragma unroll
        for (int nj = 0; nj < 4; nj++) {
            const int col = (int)nBase + n0 + nj * 8 + gc;
            const float bx = __ldg(&bias[col]);
            const float by = __ldg(&bias[col + 1]);
            float v0 = acc[mi][nj][0] + bx;
            float v1 = acc[mi][nj][1] + by;
            float v2 = acc[mi][nj][2] + bx;
            float v3 = acc[mi][nj][3] + by;
            if (RELU) {
                v0 = fmaxf(v0, 0.f); v1 = fmaxf(v1, 0.f);
                v2 = fmaxf(v2, 0.f); v3 = fmaxf(v3, 0.f);
            }
            if (MODE == 0) {
                *(float2*)(F0 + row0 * GN + col)       = make_float2(v0, v1);
                *(float2*)(F0 + (row0 + 8) * GN + col) = make_float2(v2, v3);
            } else if (MODE == 1) {
                store_split_pair(Ho, Lo, row0 * GN + col, v0, v1);
                store_split_pair(Ho, Lo, (row0 + 8) * GN + col, v2, v3);
            } else {
                store_a2_pair(A2out, row0, col, v0, v1);
                store_a2_pair(A2out, row0 + 8, col, v2, v3);
            }
        }
    }
}

// ---------------------------------------------------------------------------
// HMMA flash attention: CTA = 128 queries of one head.
// S = qh*kh + ql*kh (fp16 2-term split; dropped q*kl ~2^-12), P=exp(S/8) fp32,
// no max-sub (logits small, inputs >= 0). P packed fp16 in-register for P*V.
// Output written directly in A2 [h|l] layout for FC1.
// ---------------------------------------------------------------------------
constexpr int AST = 72;                       // smem row stride (fp16)
constexpr int SQH = 0;
constexpr int SQL = 128 * AST;
constexpr int SKV0 = 2 * 128 * AST;
constexpr int STG = 2 * 64 * AST;             // per-stage elems (kh, v)
constexpr int ATT_DSMEM = (SKV0 + 2 * STG) * 2;  // 73728 bytes

__global__ __launch_bounds__(256)
void attn_mma(const __half* __restrict__ qh, const __half* __restrict__ ql,
              const __half* __restrict__ kh, const __half* __restrict__ vh,
              __half* __restrict__ a2out)
{
    extern __shared__ __align__(16) __half smb[];
    const uint32_t sb = smem_to_u32(smb);

    const int tid = threadIdx.x;
    const int wid = tid >> 5;
    const int lid = tid & 31;
    const int m0 = wid * 16;

    const int head = blockIdx.x;
    const int bt = head >> 3;
    const int hk = head & 7;
    const size_t qrow0 = (size_t)bt * 512 + blockIdx.y * 128;
    const size_t krow0 = (size_t)bt * 512;
    const int colb = hk * 64;

    const int seg = lid >> 3, lrow = lid & 7;
    const int a_roff = lrow + ((seg & 1) << 3);
    const int a_coff = (seg >> 1) << 3;
    const int b_roff = lrow + ((seg >> 1) << 3);
    const int b_coff = (seg & 1) << 3;
    const int v_roff = lrow + ((seg & 1) << 3);
    const int v_coff = (seg >> 1) << 3;

    // ---- stage Q (group 0) ----
    {
#pragma unroll
        for (int t = 0; t < 4; t++) {
            int c = tid + t * 256;              // 1024 chunks per array
            int r = c >> 3, u = (c & 7) * 8;
            cp_async16(sb + (uint32_t)((SQH + r * AST + u) * 2),
                       qh + (qrow0 + r) * 512 + colb + u);
            cp_async16(sb + (uint32_t)((SQL + r * AST + u) * 2),
                       ql + (qrow0 + r) * 512 + colb + u);
        }
        CP_COMMIT();
    }
    auto stage_kv = [&](int kt, int buf) {
        const size_t kr = krow0 + kt * 64;
        const uint32_t b = SKV0 + buf * STG;
#pragma unroll
        for (int t = 0; t < 2; t++) {
            int c = tid + t * 256;              // 512 chunks per array
            int r = c >> 3, u = (c & 7) * 8;
            cp_async16(sb + (uint32_t)((b + r * AST + u) * 2),
                       kh + (kr + r) * 512 + colb + u);
            cp_async16(sb + (uint32_t)((b + 64 * AST + r * AST + u) * 2),
                       vh + (kr + r) * 512 + colb + u);
        }
        CP_COMMIT();
    };

    stage_kv(0, 0);
    CP_WAIT(1);          // Q complete
    __syncthreads();

    // ---- Q fragments ----
    uint32_t qfh[4][4], qfl[4][4];
#pragma unroll
    for (int ks = 0; ks < 4; ks++) {
        ldsm_x4(qfh[ks][0], qfh[ks][1], qfh[ks][2], qfh[ks][3],
                sb + (uint32_t)(((SQH + (m0 + a_roff) * AST) + ks * 16 + a_coff) * 2));
        ldsm_x4(qfl[ks][0], qfl[ks][1], qfl[ks][2], qfl[ks][3],
                sb + (uint32_t)(((SQL + (m0 + a_roff) * AST) + ks * 16 + a_coff) * 2));
    }

    float oacc[8][4];
#pragma unroll
    for (int j = 0; j < 8; j++)
#pragma unroll
        for (int c = 0; c < 4; c++) oacc[j][c] = 0.0f;
    float rs0 = 0.f, rs1 = 0.f;

    for (int kt = 0; kt < 8; kt++) {
        if (kt + 1 < 8) {
            stage_kv(kt + 1, (kt + 1) & 1);
            CP_WAIT(1);
        } else {
            CP_WAIT(0);
        }
        __syncthreads();

        const uint32_t base = SKV0 + (kt & 1) * STG;

        // --- S = Q K^T (2-term split) ---
        float sacc[8][4];
#pragma unroll
        for (int j = 0; j < 8; j++)
#pragma unroll
            for (int c = 0; c < 4; c++) sacc[j][c] = 0.0f;

#pragma unroll
        for (int ks = 0; ks < 4; ks++) {
            uint32_t kb[4][4];
#pragma unroll
            for (int j = 0; j < 4; j++)
                ldsm_x4(kb[j][0], kb[j][1], kb[j][2], kb[j][3],
                        sb + (uint32_t)(((base + (j * 16 + b_roff) * AST) + ks * 16 + b_coff) * 2));
#pragma unroll
            for (int j = 0; j < 4; j++) {
                mma16816(sacc[2 * j],     qfh[ks], &kb[j][0]);
                mma16816(sacc[2 * j + 1], qfh[ks], &kb[j][2]);
                mma16816(sacc[2 * j],     qfl[ks], &kb[j][0]);
                mma16816(sacc[2 * j + 1], qfl[ks], &kb[j][2]);
            }
        }

        // --- P = exp(S/8), rowsums ---
#pragma unroll
        for (int j = 0; j < 8; j++) {
            sacc[j][0] = __expf(sacc[j][0] * 0.125f);
            sacc[j][1] = __expf(sacc[j][1] * 0.125f);
            sacc[j][2] = __expf(sacc[j][2] * 0.125f);
            sacc[j][3] = __expf(sacc[j][3] * 0.125f);
            rs0 += sacc[j][0] + sacc[j][1];
            rs1 += sacc[j][2] + sacc[j][3];
        }

        // --- O += P V ---
#pragma unroll
        for (int pk = 0; pk < 4; pk++) {
            uint32_t pa[4];
            pa[0] = pack_f16x2(sacc[2 * pk][0],     sacc[2 * pk][1]);
            pa[1] = pack_f16x2(sacc[2 * pk][2],     sacc[2 * pk][3]);
            pa[2] = pack_f16x2(sacc[2 * pk + 1][0], sacc[2 * pk + 1][1]);
            pa[3] = pack_f16x2(sacc[2 * pk + 1][2], sacc[2 * pk + 1][3]);
            uint32_t vb[4][4];
#pragma unroll
            for (int dj = 0; dj < 4; dj++)
                ldsm_x4_t(vb[dj][0], vb[dj][1], vb[dj][2], vb[dj][3],
                          sb + (uint32_t)(((base + 64 * AST + (pk * 16 + v_roff) * AST) + dj * 16 + v_coff) * 2));
#pragma unroll
            for (int dj = 0; dj < 4; dj++) {
                mma16816(oacc[2 * dj],     pa, &vb[dj][0]);
                mma16816(oacc[2 * dj + 1], pa, &vb[dj][2]);
            }
        }
        __syncthreads();
    }

    // --- row-sum reduce across quad lanes ---
    rs0 += __shfl_xor_sync(0xFFFFFFFFu, rs0, 1);
    rs0 += __shfl_xor_sync(0xFFFFFFFFu, rs0, 2);
    rs1 += __shfl_xor_sync(0xFFFFFFFFu, rs1, 1);
    rs1 += __shfl_xor_sync(0xFFFFFFFFu, rs1, 2);
    const float rinv0 = 1.0f / rs0;
    const float rinv1 = 1.0f / rs1;

    // --- normalize + write A2 [h|l] ---
    const int gr = lid >> 2;
    const int gc = (lid & 3) * 2;
    const size_t row0 = qrow0 + m0 + gr;
#pragma unroll
    for (int nj = 0; nj < 8; nj++) {
        const int col = colb + nj * 8 + gc;
        store_a2_pair(a2out, row0,     col, oacc[nj][0] * rinv0, oacc[nj][1] * rinv0);
        store_a2_pair(a2out, row0 + 8, col, oacc[nj][2] * rinv1, oacc[nj][3] * rinv1);
    }
}

// ---------------------------------------------------------------------------
// Launch
// ---------------------------------------------------------------------------
extern "C" void kernel_launch(void* const* d_in, const int* in_sizes, int n_in,
                              void* d_out, int out_size)
{
    (void)in_sizes; (void)n_in; (void)out_size;
    const float* X  = (const float*)d_in[0];
    const float* Wq = (const float*)d_in[2];
    const float* bq = (const float*)d_in[3];
    const float* Wk = (const float*)d_in[4];
    const float* bk = (const float*)d_in[5];
    const float* Wv = (const float*)d_in[6];
    const float* bv = (const float*)d_in[7];
    const float* W1 = (const float*)d_in[8];
    const float* b1 = (const float*)d_in[9];
    const float* W2 = (const float*)d_in[10];
    const float* b2 = (const float*)d_in[11];
    float* out = (float*)d_out;

    __half *a2a, *a2b, *w2, *qh, *ql, *kh, *vh;
    cudaGetSymbolAddress((void**)&a2a, g_a2a);
    cudaGetSymbolAddress((void**)&a2b, g_a2b);
    cudaGetSymbolAddress((void**)&w2,  g_w2);
    cudaGetSymbolAddress((void**)&qh,  g_qh);
    cudaGetSymbolAddress((void**)&ql,  g_ql);
    cudaGetSymbolAddress((void**)&kh,  g_kh);
    cudaGetSymbolAddress((void**)&vh,  g_vh);
    const size_t WSZ = (size_t)GN * 512;

    cudaFuncSetAttribute((const void*)gemm_mma<true, 1>,
                         cudaFuncAttributeMaxDynamicSharedMemorySize, GEMM_DSMEM);
    cudaFuncSetAttribute((const void*)gemm_mma<true, 2>,
                         cudaFuncAttributeMaxDynamicSharedMemorySize, GEMM_DSMEM);
    cudaFuncSetAttribute((const void*)gemm_mma<false, 0>,
                         cudaFuncAttributeMaxDynamicSharedMemorySize, GEMM_DSMEM);
    cudaFuncSetAttribute((const void*)attn_mma,
                         cudaFuncAttributeMaxDynamicSharedMemorySize, ATT_DSMEM);

    dim3 blk(256);
    dim3 gW(512 * 512 / 256);
    dim3 gAct((unsigned)((size_t)GM * 128 / 256));
    dim3 gQKV(GN / BN, GM / BM, 3);
    dim3 gFC(GN / BN, GM / BM, 1);
    dim3 gAtt(BT * KH, 4);

    conv_w<<<gW, blk>>>(Wq, w2 + 0 * WSZ);
    conv_w<<<gW, blk>>>(Wk, w2 + 1 * WSZ);
    conv_w<<<gW, blk>>>(Wv, w2 + 2 * WSZ);
    conv_w<<<gW, blk>>>(W1, w2 + 3 * WSZ);
    conv_w<<<gW, blk>>>(W2, w2 + 4 * WSZ);

    // 1) split X -> a2a; QKV GEMM -> q split, k/v single
    conv_act<<<gAct, blk>>>(X, a2a);
    gemm_mma<true, 1><<<gQKV, blk, GEMM_DSMEM>>>(a2a, w2, w2 + WSZ, w2 + 2 * WSZ,
                                                 bq, bk, bv, nullptr,
                                                 qh, ql, kh, vh, nullptr);
    // 2) attention -> a2b (A2 layout, fused)
    attn_mma<<<gAtt, blk, ATT_DSMEM>>>(qh, ql, kh, vh, a2b);
    // 3) FC1 -> a2a (A2 layout, fused, ReLU)
    gemm_mma<true, 2><<<gFC, blk, GEMM_DSMEM>>>(a2b, w2 + 3 * WSZ, w2 + 3 * WSZ, w2 + 3 * WSZ,
                                                b1, b1, b1, nullptr,
                                                nullptr, nullptr, nullptr, nullptr, a2a);
    // 4) FC2 -> out (fp32)
    gemm_mma<false, 0><<<gFC, blk, GEMM_DSMEM>>>(a2a, w2 + 4 * WSZ, w2 + 4 * WSZ, w2 + 4 * WSZ,
                                                 b2, b2, b2, out,
                                                 nullptr, nullptr, nullptr, nullptr, nullptr);
}

// round 6
// speedup vs baseline: 6.7613x; 1.6960x over previous
#include <cuda_runtime.h>
#include <cuda_fp16.h>
#include <cstdint>

// ---------------------------------------------------------------------------
// Problem constants
// ---------------------------------------------------------------------------
constexpr int Bc = 8, Tc = 12, Nc = 512;
constexpr int BT = Bc * Tc;                 // 96
constexpr int GM = BT * Nc;                 // 49152 rows
constexpr int GN = 512;
constexpr int GK = 512;
constexpr int KH = 8;

// Scratch (allocation-free rule: __device__ globals)
__device__ __half g_x [(size_t)GM * GK];
__device__ __half g_q [(size_t)GM * GK];
__device__ __half g_k [(size_t)GM * GK];
__device__ __half g_v [(size_t)GM * GK];
__device__ __half g_ao[(size_t)GM * GK];
__device__ __half g_h [(size_t)GM * GK];
__device__ __half g_w2[5 * (size_t)GN * GK];   // fp16 weights, [n][k]

__device__ __forceinline__ uint32_t smem_to_u32(const void* p) {
    uint32_t a;
    asm("{ .reg .u64 t; cvta.to.shared.u64 t, %1; cvt.u32.u64 %0, t; }" : "=r"(a) : "l"(p));
    return a;
}

// ---------------------------------------------------------------------------
// Portable tensor-core primitives (sm_80+ ISA)
// ---------------------------------------------------------------------------
__device__ __forceinline__ void ldsm_x4(uint32_t& r0, uint32_t& r1, uint32_t& r2, uint32_t& r3,
                                        uint32_t addr) {
    asm volatile("ldmatrix.sync.aligned.m8n8.x4.shared.b16 {%0,%1,%2,%3}, [%4];"
                 : "=r"(r0), "=r"(r1), "=r"(r2), "=r"(r3) : "r"(addr));
}
__device__ __forceinline__ void ldsm_x4_t(uint32_t& r0, uint32_t& r1, uint32_t& r2, uint32_t& r3,
                                          uint32_t addr) {
    asm volatile("ldmatrix.sync.aligned.m8n8.x4.trans.shared.b16 {%0,%1,%2,%3}, [%4];"
                 : "=r"(r0), "=r"(r1), "=r"(r2), "=r"(r3) : "r"(addr));
}
__device__ __forceinline__ void mma16816(float* d, const uint32_t* a, const uint32_t* b) {
    asm volatile("mma.sync.aligned.m16n8k16.row.col.f32.f16.f16.f32 "
                 "{%0,%1,%2,%3}, {%4,%5,%6,%7}, {%8,%9}, {%0,%1,%2,%3};"
                 : "+f"(d[0]), "+f"(d[1]), "+f"(d[2]), "+f"(d[3])
                 : "r"(a[0]), "r"(a[1]), "r"(a[2]), "r"(a[3]), "r"(b[0]), "r"(b[1]));
}
__device__ __forceinline__ void cp_async16(uint32_t smem_addr, const void* gptr) {
    asm volatile("cp.async.cg.shared.global [%0], [%1], 16;" :: "r"(smem_addr), "l"(gptr));
}
#define CP_COMMIT() asm volatile("cp.async.commit_group;" ::: "memory")
#define CP_WAIT(n)  asm volatile("cp.async.wait_group %0;" :: "n"(n) : "memory")

__device__ __forceinline__ uint32_t pack_f16x2(float lo, float hi) {
    uint32_t r;
    asm("cvt.rn.f16x2.f32 %0, %1, %2;" : "=r"(r) : "f"(hi), "f"(lo));
    return r;
}

// ---------------------------------------------------------------------------
// Conversion kernels
// ---------------------------------------------------------------------------
__global__ __launch_bounds__(256) void conv_x(const float* __restrict__ A,
                                              __half* __restrict__ Ah) {
    size_t i = (size_t)blockIdx.x * 256 + threadIdx.x;   // over GM*64
    size_t base = i * 8;
    float4 a0 = *(const float4*)(A + base);
    float4 a1 = *(const float4*)(A + base + 4);
    __half h[8];
    h[0] = __float2half_rn(a0.x); h[1] = __float2half_rn(a0.y);
    h[2] = __float2half_rn(a0.z); h[3] = __float2half_rn(a0.w);
    h[4] = __float2half_rn(a1.x); h[5] = __float2half_rn(a1.y);
    h[6] = __float2half_rn(a1.z); h[7] = __float2half_rn(a1.w);
    *(uint4*)(Ah + base) = *(uint4*)h;
}

// 5 weights fused: W[512k][512n] fp32 -> fp16 [n][k]
__global__ __launch_bounds__(256) void conv_w5(const float* __restrict__ W0,
                                               const float* __restrict__ W1,
                                               const float* __restrict__ W2,
                                               const float* __restrict__ W3,
                                               const float* __restrict__ W4,
                                               __half* __restrict__ dst) {
    const int z = blockIdx.y;
    const float* W = (z == 0) ? W0 : (z == 1) ? W1 : (z == 2) ? W2 : (z == 3) ? W3 : W4;
    __half* d = dst + (size_t)z * GN * GK;
    int i = blockIdx.x * 256 + threadIdx.x;   // 512*512
    int k = i >> 9, n = i & 511;
    d[(size_t)n * GK + k] = __float2half_rn(W[i]);
}

// ---------------------------------------------------------------------------
// HMMA GEMM: C[M,N] = act(A[M,512]fp16 @ W[N,512]^T + bias)
// CTA 128x128, BK=64, NIT=8, 3-stage cp.async, ONE sync per iter.
// F32OUT: fp32 to F; else fp16 to H(z).
// ---------------------------------------------------------------------------
constexpr int BM = 128, BN = 128, BK = 64;
constexpr int KST = 72;                       // padded smem stride (fp16 elems)
constexpr int NIT = GK / BK;                  // 8
constexpr int NSTG = 3;
constexpr int STG_ELEMS = (BM + BN) * KST;    // 18432
constexpr int GEMM_DSMEM = NSTG * STG_ELEMS * 2;  // 110592 B

template <bool RELU, bool F32OUT>
__global__ __launch_bounds__(256)
void gemm_mma(const __half* __restrict__ A,
              const __half* __restrict__ B0, const __half* __restrict__ B1,
              const __half* __restrict__ B2,
              const float* __restrict__ bias0, const float* __restrict__ bias1,
              const float* __restrict__ bias2,
              float* __restrict__ F,
              __half* __restrict__ H0, __half* __restrict__ H1, __half* __restrict__ H2)
{
    const int z = blockIdx.z;
    const __half* Bw  = (z == 0) ? B0 : (z == 1) ? B1 : B2;
    const float* bias = (z == 0) ? bias0 : (z == 1) ? bias1 : bias2;
    __half* Ho        = (z == 0) ? H0 : (z == 1) ? H1 : H2;

    extern __shared__ __align__(16) __half dynsm[];
    const uint32_t sbase = smem_to_u32(dynsm);

    const int tid = threadIdx.x;
    const int wid = tid >> 5;
    const int lid = tid & 31;
    const int m0 = (wid >> 2) * 64;
    const int n0 = (wid & 3) * 32;

    const size_t mBase = (size_t)blockIdx.y * BM;
    const size_t nBase = (size_t)blockIdx.x * BN;
    const __half* Ag = A + mBase * GK;
    const __half* Bg = Bw + nBase * GK;

    auto load_stage = [&](int buf, int it) {
        const int k0 = it * BK;
        const uint32_t aOff = sbase + (uint32_t)(buf * STG_ELEMS) * 2;
        const uint32_t bOff = aOff + (uint32_t)(BM * KST) * 2;
#pragma unroll
        for (int p = 0; p < 4; p++) {
            int idx = tid + p * 256;            // 0..1023
            int r = idx >> 3, u = (idx & 7) * 8;
            uint32_t soff = (uint32_t)((r * KST + u) * 2);
            cp_async16(aOff + soff, Ag + (size_t)r * GK + k0 + u);
            cp_async16(bOff + soff, Bg + (size_t)r * GK + k0 + u);
        }
        CP_COMMIT();
    };

    float acc[4][4][4];
#pragma unroll
    for (int i = 0; i < 4; i++)
#pragma unroll
        for (int j = 0; j < 4; j++)
#pragma unroll
            for (int c = 0; c < 4; c++) acc[i][j][c] = 0.0f;

    const int seg = lid >> 3, lrow = lid & 7;
    const int a_roff = lrow + ((seg & 1) << 3);
    const int a_coff = (seg >> 1) << 3;
    const int b_roff = lrow + ((seg >> 1) << 3);
    const int b_coff = (seg & 1) << 3;

    load_stage(0, 0);
    load_stage(1, 1);

    for (int it = 0; it < NIT; ++it) {
        CP_WAIT(1);                 // stage `it` complete
        __syncthreads();            // publish stage `it`; gate buffer reuse
        if (it + 2 < NIT) load_stage((it + 2) % NSTG, it + 2);

        const uint32_t aB = sbase + (uint32_t)((it % NSTG) * STG_ELEMS) * 2;
        const uint32_t bB = aB + (uint32_t)(BM * KST) * 2;

#pragma unroll
        for (int kk = 0; kk < 4; kk++) {
            uint32_t ra[4][4], rb[2][4];
#pragma unroll
            for (int mi = 0; mi < 4; mi++) {
                uint32_t addr = aB + (uint32_t)(((m0 + mi * 16 + a_roff) * KST + kk * 16 + a_coff) * 2);
                ldsm_x4(ra[mi][0], ra[mi][1], ra[mi][2], ra[mi][3], addr);
            }
#pragma unroll
            for (int nj = 0; nj < 2; nj++) {
                uint32_t addr = bB + (uint32_t)(((n0 + nj * 16 + b_roff) * KST + kk * 16 + b_coff) * 2);
                ldsm_x4(rb[nj][0], rb[nj][1], rb[nj][2], rb[nj][3], addr);
            }
#pragma unroll
            for (int mi = 0; mi < 4; mi++)
#pragma unroll
                for (int nj = 0; nj < 4; nj++)
                    mma16816(acc[mi][nj], ra[mi], &rb[nj >> 1][(nj & 1) * 2]);
        }
    }

    // epilogue
    const int gr = lid >> 2;
    const int gc = (lid & 3) * 2;
#pragma unroll
    for (int mi = 0; mi < 4; mi++) {
        const size_t row0 = mBase + m0 + mi * 16 + gr;
#pragma unroll
        for (int nj = 0; nj < 4; nj++) {
            const int col = (int)nBase + n0 + nj * 8 + gc;
            const float bx = __ldg(&bias[col]);
            const float by = __ldg(&bias[col + 1]);
            float v0 = acc[mi][nj][0] + bx;
            float v1 = acc[mi][nj][1] + by;
            float v2 = acc[mi][nj][2] + bx;
            float v3 = acc[mi][nj][3] + by;
            if (RELU) {
                v0 = fmaxf(v0, 0.f); v1 = fmaxf(v1, 0.f);
                v2 = fmaxf(v2, 0.f); v3 = fmaxf(v3, 0.f);
            }
            if (F32OUT) {
                *(float2*)(F + row0 * GN + col)       = make_float2(v0, v1);
                *(float2*)(F + (row0 + 8) * GN + col) = make_float2(v2, v3);
            } else {
                *(uint32_t*)(Ho + row0 * GN + col)       = pack_f16x2(v0, v1);
                *(uint32_t*)(Ho + (row0 + 8) * GN + col) = pack_f16x2(v2, v3);
            }
        }
    }
}

// ---------------------------------------------------------------------------
// HMMA flash attention: CTA = 128 queries of one head, plain fp16.
// S = q k^T, P = exp(S/8) in fp32 (no max-sub: inputs >= 0, logits small),
// P packed fp16 in-register for P*V. 3-stage KV pipeline, one sync per tile.
// ---------------------------------------------------------------------------
constexpr int AST = 72;                       // smem row stride (fp16)
constexpr int SQ = 0;
constexpr int SKV0 = 128 * AST;
constexpr int STG = 2 * 64 * AST;             // per-stage elems (k, v)
constexpr int ATT_DSMEM = (SKV0 + 3 * STG) * 2;  // 73728 B

__global__ __launch_bounds__(256)
void attn_mma(const __half* __restrict__ qg, const __half* __restrict__ kg,
              const __half* __restrict__ vg, __half* __restrict__ og)
{
    extern __shared__ __align__(16) __half smb[];
    const uint32_t sb = smem_to_u32(smb);

    const int tid = threadIdx.x;
    const int wid = tid >> 5;
    const int lid = tid & 31;
    const int m0 = wid * 16;

    const int head = blockIdx.x;
    const int bt = head >> 3;
    const int hk = head & 7;
    const size_t qrow0 = (size_t)bt * 512 + blockIdx.y * 128;
    const size_t krow0 = (size_t)bt * 512;
    const int colb = hk * 64;

    const int seg = lid >> 3, lrow = lid & 7;
    const int a_roff = lrow + ((seg & 1) << 3);
    const int a_coff = (seg >> 1) << 3;
    const int b_roff = lrow + ((seg >> 1) << 3);
    const int b_coff = (seg & 1) << 3;
    const int v_roff = lrow + ((seg & 1) << 3);
    const int v_coff = (seg >> 1) << 3;

    // ---- stage Q (own commit group) ----
    {
#pragma reunroll
#pragma unroll
        for (int t = 0; t < 4; t++) {
            int c = tid + t * 256;              // 1024 chunks
            int r = c >> 3, u = (c & 7) * 8;
            cp_async16(sb + (uint32_t)((SQ + r * AST + u) * 2),
                       qg + (qrow0 + r) * 512 + colb + u);
        }
        CP_COMMIT();
    }
    auto stage_kv = [&](int kt) {
        const size_t kr = krow0 + kt * 64;
        const uint32_t b = SKV0 + (kt % 3) * STG;
#pragma unroll
        for (int t = 0; t < 2; t++) {
            int c = tid + t * 256;              // 512 chunks per array
            int r = c >> 3, u = (c & 7) * 8;
            cp_async16(sb + (uint32_t)((b + r * AST + u) * 2),
                       kg + (kr + r) * 512 + colb + u);
            cp_async16(sb + (uint32_t)((b + 64 * AST + r * AST + u) * 2),
                       vg + (kr + r) * 512 + colb + u);
        }
        CP_COMMIT();
    };

    stage_kv(0);
    stage_kv(1);
    CP_WAIT(2);          // Q complete
    __syncthreads();

    // ---- Q fragments ----
    uint32_t qf[4][4];
#pragma unroll
    for (int ks = 0; ks < 4; ks++)
        ldsm_x4(qf[ks][0], qf[ks][1], qf[ks][2], qf[ks][3],
                sb + (uint32_t)(((SQ + (m0 + a_roff) * AST) + ks * 16 + a_coff) * 2));

    float oacc[8][4];
#pragma unroll
    for (int j = 0; j < 8; j++)
#pragma unroll
        for (int c = 0; c < 4; c++) oacc[j][c] = 0.0f;
    float rs0 = 0.f, rs1 = 0.f;

    for (int kt = 0; kt < 8; kt++) {
        CP_WAIT(1);                 // stage kt ready
        __syncthreads();
        if (kt + 2 < 8) stage_kv(kt + 2);

        const uint32_t base = SKV0 + (kt % 3) * STG;

        // --- S = Q K^T ---
        float sacc[8][4];
#pragma unroll
        for (int j = 0; j < 8; j++)
#pragma unroll
            for (int c = 0; c < 4; c++) sacc[j][c] = 0.0f;

#pragma unroll
        for (int ks = 0; ks < 4; ks++) {
            uint32_t kb[4][4];
#pragma unroll
            for (int j = 0; j < 4; j++)
                ldsm_x4(kb[j][0], kb[j][1], kb[j][2], kb[j][3],
                        sb + (uint32_t)(((base + (j * 16 + b_roff) * AST) + ks * 16 + b_coff) * 2));
#pragma unroll
            for (int j = 0; j < 4; j++) {
                mma16816(sacc[2 * j],     qf[ks], &kb[j][0]);
                mma16816(sacc[2 * j + 1], qf[ks], &kb[j][2]);
            }
        }

        // --- P = exp(S/8), rowsums ---
#pragma unroll
        for (int j = 0; j < 8; j++) {
            sacc[j][0] = __expf(sacc[j][0] * 0.125f);
            sacc[j][1] = __expf(sacc[j][1] * 0.125f);
            sacc[j][2] = __expf(sacc[j][2] * 0.125f);
            sacc[j][3] = __expf(sacc[j][3] * 0.125f);
            rs0 += sacc[j][0] + sacc[j][1];
            rs1 += sacc[j][2] + sacc[j][3];
        }

        // --- O += P V ---
#pragma unroll
        for (int pk = 0; pk < 4; pk++) {
            uint32_t pa[4];
            pa[0] = pack_f16x2(sacc[2 * pk][0],     sacc[2 * pk][1]);
            pa[1] = pack_f16x2(sacc[2 * pk][2],     sacc[2 * pk][3]);
            pa[2] = pack_f16x2(sacc[2 * pk + 1][0], sacc[2 * pk + 1][1]);
            pa[3] = pack_f16x2(sacc[2 * pk + 1][2], sacc[2 * pk + 1][3]);
            uint32_t vb[4][4];
#pragma unroll
            for (int dj = 0; dj < 4; dj++)
                ldsm_x4_t(vb[dj][0], vb[dj][1], vb[dj][2], vb[dj][3],
                          sb + (uint32_t)(((base + 64 * AST + (pk * 16 + v_roff) * AST) + dj * 16 + v_coff) * 2));
#pragma unroll
            for (int dj = 0; dj < 4; dj++) {
                mma16816(oacc[2 * dj],     pa, &vb[dj][0]);
                mma16816(oacc[2 * dj + 1], pa, &vb[dj][2]);
            }
        }
    }

    // --- row-sum reduce across quad lanes ---
    rs0 += __shfl_xor_sync(0xFFFFFFFFu, rs0, 1);
    rs0 += __shfl_xor_sync(0xFFFFFFFFu, rs0, 2);
    rs1 += __shfl_xor_sync(0xFFFFFFFFu, rs1, 1);
    rs1 += __shfl_xor_sync(0xFFFFFFFFu, rs1, 2);
    const float rinv0 = 1.0f / rs0;
    const float rinv1 = 1.0f / rs1;

    // --- normalize + write fp16 ---
    const int gr = lid >> 2;
    const int gc = (lid & 3) * 2;
    const size_t row0 = qrow0 + m0 + gr;
#pragma unroll
    for (int nj = 0; nj < 8; nj++) {
        const int col = colb + nj * 8 + gc;
        *(uint32_t*)(og + row0 * 512 + col) =
            pack_f16x2(oacc[nj][0] * rinv0, oacc[nj][1] * rinv0);
        *(uint32_t*)(og + (row0 + 8) * 512 + col) =
            pack_f16x2(oacc[nj][2] * rinv1, oacc[nj][3] * rinv1);
    }
}

// ---------------------------------------------------------------------------
// Launch
// ---------------------------------------------------------------------------
extern "C" void kernel_launch(void* const* d_in, const int* in_sizes, int n_in,
                              void* d_out, int out_size)
{
    (void)in_sizes; (void)n_in; (void)out_size;
    const float* X  = (const float*)d_in[0];
    const float* Wq = (const float*)d_in[2];
    const float* bq = (const float*)d_in[3];
    const float* Wk = (const float*)d_in[4];
    const float* bk = (const float*)d_in[5];
    const float* Wv = (const float*)d_in[6];
    const float* bv = (const float*)d_in[7];
    const float* W1 = (const float*)d_in[8];
    const float* b1 = (const float*)d_in[9];
    const float* W2 = (const float*)d_in[10];
    const float* b2 = (const float*)d_in[11];
    float* out = (float*)d_out;

    __half *x, *q, *k, *v, *ao, *h, *w2;
    cudaGetSymbolAddress((void**)&x,  g_x);
    cudaGetSymbolAddress((void**)&q,  g_q);
    cudaGetSymbolAddress((void**)&k,  g_k);
    cudaGetSymbolAddress((void**)&v,  g_v);
    cudaGetSymbolAddress((void**)&ao, g_ao);
    cudaGetSymbolAddress((void**)&h,  g_h);
    cudaGetSymbolAddress((void**)&w2, g_w2);
    const size_t WSZ = (size_t)GN * GK;

    cudaFuncSetAttribute((const void*)gemm_mma<true, false>,
                         cudaFuncAttributeMaxDynamicSharedMemorySize, GEMM_DSMEM);
    cudaFuncSetAttribute((const void*)gemm_mma<false, true>,
                         cudaFuncAttributeMaxDynamicSharedMemorySize, GEMM_DSMEM);
    cudaFuncSetAttribute((const void*)attn_mma,
                         cudaFuncAttributeMaxDynamicSharedMemorySize, ATT_DSMEM);

    dim3 blk(256);
    dim3 gX((unsigned)((size_t)GM * 64 / 256));
    dim3 gW(512 * 512 / 256, 5);
    dim3 gQKV(GN / BN, GM / BM, 3);
    dim3 gFC(GN / BN, GM / BM, 1);
    dim3 gAtt(BT * KH, 4);

    conv_x<<<gX, blk>>>(X, x);
    conv_w5<<<gW, blk>>>(Wq, Wk, Wv, W1, W2, w2);

    // 1) QKV (fp16 out)
    gemm_mma<true, false><<<gQKV, blk, GEMM_DSMEM>>>(x, w2, w2 + WSZ, w2 + 2 * WSZ,
                                                     bq, bk, bv, nullptr, q, k, v);
    // 2) attention -> ao (fp16)
    attn_mma<<<gAtt, blk, ATT_DSMEM>>>(q, k, v, ao);
    // 3) FC1 -> h (fp16, ReLU)
    gemm_mma<true, false><<<gFC, blk, GEMM_DSMEM>>>(ao, w2 + 3 * WSZ, w2 + 3 * WSZ, w2 + 3 * WSZ,
                                                    b1, b1, b1, nullptr, h, h, h);
    // 4) FC2 -> out (fp32)
    gemm_mma<false, true><<<gFC, blk, GEMM_DSMEM>>>(h, w2 + 4 * WSZ, w2 + 4 * WSZ, w2 + 4 * WSZ,
                                                    b2, b2, b2, out,
                                                    nullptr, nullptr, nullptr);
}

// round 7
// speedup vs baseline: 7.3516x; 1.0873x over previous
#include <cuda_runtime.h>
#include <cuda_fp16.h>
#include <cstdint>

// ---------------------------------------------------------------------------
// Problem constants
// ---------------------------------------------------------------------------
constexpr int Bc = 8, Tc = 12, Nc = 512;
constexpr int BT = Bc * Tc;                 // 96
constexpr int GM = BT * Nc;                 // 49152 rows
constexpr int GN = 512;
constexpr int GK = 512;
constexpr int KH = 8;

// Scratch (allocation-free rule: __device__ globals)
__device__ __half g_x [(size_t)GM * GK];
__device__ __half g_q [(size_t)GM * GK];
__device__ __half g_k [(size_t)GM * GK];
__device__ __half g_v [(size_t)GM * GK];
__device__ __half g_ao[(size_t)GM * GK];
__device__ __half g_h [(size_t)GM * GK];
__device__ __half g_w2[5 * (size_t)GN * GK];   // fp16 weights, [n][k]

__device__ __forceinline__ uint32_t smem_to_u32(const void* p) {
    uint32_t a;
    asm("{ .reg .u64 t; cvta.to.shared.u64 t, %1; cvt.u32.u64 %0, t; }" : "=r"(a) : "l"(p));
    return a;
}

// ---------------------------------------------------------------------------
// Portable tensor-core primitives (sm_80+ ISA)
// ---------------------------------------------------------------------------
__device__ __forceinline__ void ldsm_x4(uint32_t& r0, uint32_t& r1, uint32_t& r2, uint32_t& r3,
                                        uint32_t addr) {
    asm volatile("ldmatrix.sync.aligned.m8n8.x4.shared.b16 {%0,%1,%2,%3}, [%4];"
                 : "=r"(r0), "=r"(r1), "=r"(r2), "=r"(r3) : "r"(addr));
}
__device__ __forceinline__ void ldsm_x4_t(uint32_t& r0, uint32_t& r1, uint32_t& r2, uint32_t& r3,
                                          uint32_t addr) {
    asm volatile("ldmatrix.sync.aligned.m8n8.x4.trans.shared.b16 {%0,%1,%2,%3}, [%4];"
                 : "=r"(r0), "=r"(r1), "=r"(r2), "=r"(r3) : "r"(addr));
}
__device__ __forceinline__ void mma16816(float* d, const uint32_t* a, const uint32_t* b) {
    asm volatile("mma.sync.aligned.m16n8k16.row.col.f32.f16.f16.f32 "
                 "{%0,%1,%2,%3}, {%4,%5,%6,%7}, {%8,%9}, {%0,%1,%2,%3};"
                 : "+f"(d[0]), "+f"(d[1]), "+f"(d[2]), "+f"(d[3])
                 : "r"(a[0]), "r"(a[1]), "r"(a[2]), "r"(a[3]), "r"(b[0]), "r"(b[1]));
}
__device__ __forceinline__ void cp_async16(uint32_t smem_addr, const void* gptr) {
    asm volatile("cp.async.cg.shared.global [%0], [%1], 16;" :: "r"(smem_addr), "l"(gptr));
}
#define CP_COMMIT() asm volatile("cp.async.commit_group;" ::: "memory")
#define CP_WAIT(n)  asm volatile("cp.async.wait_group %0;" :: "n"(n) : "memory")

__device__ __forceinline__ uint32_t pack_f16x2(float lo, float hi) {
    uint32_t r;
    asm("cvt.rn.f16x2.f32 %0, %1, %2;" : "=r"(r) : "f"(hi), "f"(lo));
    return r;
}

// ---------------------------------------------------------------------------
// Conversion kernels
// ---------------------------------------------------------------------------
__global__ __launch_bounds__(256) void conv_x(const float* __restrict__ A,
                                              __half* __restrict__ Ah) {
    size_t i = (size_t)blockIdx.x * 256 + threadIdx.x;   // over GM*64
    size_t base = i * 8;
    float4 a0 = *(const float4*)(A + base);
    float4 a1 = *(const float4*)(A + base + 4);
    __half h[8];
    h[0] = __float2half_rn(a0.x); h[1] = __float2half_rn(a0.y);
    h[2] = __float2half_rn(a0.z); h[3] = __float2half_rn(a0.w);
    h[4] = __float2half_rn(a1.x); h[5] = __float2half_rn(a1.y);
    h[6] = __float2half_rn(a1.z); h[7] = __float2half_rn(a1.w);
    *(uint4*)(Ah + base) = *(uint4*)h;
}

// 5 weights fused: W[512k][512n] fp32 -> fp16 [n][k]
__global__ __launch_bounds__(256) void conv_w5(const float* __restrict__ W0,
                                               const float* __restrict__ W1,
                                               const float* __restrict__ W2,
                                               const float* __restrict__ W3,
                                               const float* __restrict__ W4,
                                               __half* __restrict__ dst) {
    const int z = blockIdx.y;
    const float* W = (z == 0) ? W0 : (z == 1) ? W1 : (z == 2) ? W2 : (z == 3) ? W3 : W4;
    __half* d = dst + (size_t)z * GN * GK;
    int i = blockIdx.x * 256 + threadIdx.x;   // 512*512
    int k = i >> 9, n = i & 511;
    d[(size_t)n * GK + k] = __float2half_rn(W[i]);
}

// ---------------------------------------------------------------------------
// HMMA GEMM: C[M,N] = act(A[M,512]fp16 @ W[N,512]^T + bias)
// CTA 128x128, BK=64, NIT=8, 3-stage cp.async, ONE sync per iter.
// NZ weight variants encoded fastest-varying in blockIdx.x (L2 A-reuse).
// __launch_bounds__(256,2): guarantee 2 CTAs/SM (regs <= 128).
// ---------------------------------------------------------------------------
constexpr int BM = 128, BN = 128, BK = 64;
constexpr int KST = 72;                       // padded smem stride (fp16 elems)
constexpr int NIT = GK / BK;                  // 8
constexpr int NSTG = 3;
constexpr int STG_ELEMS = (BM + BN) * KST;    // 18432
constexpr int GEMM_DSMEM = NSTG * STG_ELEMS * 2;  // 110592 B (2 CTAs = 221 KB <= 228)

template <bool RELU, bool F32OUT, int NZ>
__global__ __launch_bounds__(256, 2)
void gemm_mma(const __half* __restrict__ A,
              const __half* __restrict__ B0, const __half* __restrict__ B1,
              const __half* __restrict__ B2,
              const float* __restrict__ bias0, const float* __restrict__ bias1,
              const float* __restrict__ bias2,
              float* __restrict__ F,
              __half* __restrict__ H0, __half* __restrict__ H1, __half* __restrict__ H2)
{
    const int z  = (NZ == 1) ? 0 : ((int)blockIdx.x % NZ);
    const int nb = (NZ == 1) ? (int)blockIdx.x : ((int)blockIdx.x / NZ);
    const __half* Bw  = (z == 0) ? B0 : (z == 1) ? B1 : B2;
    const float* bias = (z == 0) ? bias0 : (z == 1) ? bias1 : bias2;
    __half* Ho        = (z == 0) ? H0 : (z == 1) ? H1 : H2;

    extern __shared__ __align__(16) __half dynsm[];
    const uint32_t sbase = smem_to_u32(dynsm);

    const int tid = threadIdx.x;
    const int wid = tid >> 5;
    const int lid = tid & 31;
    const int m0 = (wid >> 2) * 64;
    const int n0 = (wid & 3) * 32;

    const size_t mBase = (size_t)blockIdx.y * BM;
    const size_t nBase = (size_t)nb * BN;
    const __half* Ag = A + mBase * GK;
    const __half* Bg = Bw + nBase * GK;

    auto load_stage = [&](int buf, int it) {
        const int k0 = it * BK;
        const uint32_t aOff = sbase + (uint32_t)(buf * STG_ELEMS) * 2;
        const uint32_t bOff = aOff + (uint32_t)(BM * KST) * 2;
#pragma unroll
        for (int p = 0; p < 4; p++) {
            int idx = tid + p * 256;            // 0..1023
            int r = idx >> 3, u = (idx & 7) * 8;
            uint32_t soff = (uint32_t)((r * KST + u) * 2);
            cp_async16(aOff + soff, Ag + (size_t)r * GK + k0 + u);
            cp_async16(bOff + soff, Bg + (size_t)r * GK + k0 + u);
        }
        CP_COMMIT();
    };

    float acc[4][4][4];
#pragma unroll
    for (int i = 0; i < 4; i++)
#pragma unroll
        for (int j = 0; j < 4; j++)
#pragma unroll
            for (int c = 0; c < 4; c++) acc[i][j][c] = 0.0f;

    const int seg = lid >> 3, lrow = lid & 7;
    const int a_roff = lrow + ((seg & 1) << 3);
    const int a_coff = (seg >> 1) << 3;
    const int b_roff = lrow + ((seg >> 1) << 3);
    const int b_coff = (seg & 1) << 3;

    load_stage(0, 0);
    load_stage(1, 1);

    for (int it = 0; it < NIT; ++it) {
        CP_WAIT(1);                 // stage `it` complete
        __syncthreads();            // publish stage `it`; gate buffer reuse
        if (it + 2 < NIT) load_stage((it + 2) % NSTG, it + 2);

        const uint32_t aB = sbase + (uint32_t)((it % NSTG) * STG_ELEMS) * 2;
        const uint32_t bB = aB + (uint32_t)(BM * KST) * 2;

#pragma unroll
        for (int kk = 0; kk < 4; kk++) {
            uint32_t ra[4][4], rb[2][4];
#pragma unroll
            for (int mi = 0; mi < 4; mi++) {
                uint32_t addr = aB + (uint32_t)(((m0 + mi * 16 + a_roff) * KST + kk * 16 + a_coff) * 2);
                ldsm_x4(ra[mi][0], ra[mi][1], ra[mi][2], ra[mi][3], addr);
            }
#pragma unroll
            for (int nj = 0; nj < 2; nj++) {
                uint32_t addr = bB + (uint32_t)(((n0 + nj * 16 + b_roff) * KST + kk * 16 + b_coff) * 2);
                ldsm_x4(rb[nj][0], rb[nj][1], rb[nj][2], rb[nj][3], addr);
            }
#pragma unroll
            for (int mi = 0; mi < 4; mi++)
#pragma unroll
                for (int nj = 0; nj < 4; nj++)
                    mma16816(acc[mi][nj], ra[mi], &rb[nj >> 1][(nj & 1) * 2]);
        }
    }

    // epilogue
    const int gr = lid >> 2;
    const int gc = (lid & 3) * 2;
#pragma unroll
    for (int mi = 0; mi < 4; mi++) {
        const size_t row0 = mBase + m0 + mi * 16 + gr;
#pragma unroll
        for (int nj = 0; nj < 4; nj++) {
            const int col = (int)nBase + n0 + nj * 8 + gc;
            const float bx = __ldg(&bias[col]);
            const float by = __ldg(&bias[col + 1]);
            float v0 = acc[mi][nj][0] + bx;
            float v1 = acc[mi][nj][1] + by;
            float v2 = acc[mi][nj][2] + bx;
            float v3 = acc[mi][nj][3] + by;
            if (RELU) {
                v0 = fmaxf(v0, 0.f); v1 = fmaxf(v1, 0.f);
                v2 = fmaxf(v2, 0.f); v3 = fmaxf(v3, 0.f);
            }
            if (F32OUT) {
                *(float2*)(F + row0 * GN + col)       = make_float2(v0, v1);
                *(float2*)(F + (row0 + 8) * GN + col) = make_float2(v2, v3);
            } else {
                *(uint32_t*)(Ho + row0 * GN + col)       = pack_f16x2(v0, v1);
                *(uint32_t*)(Ho + (row0 + 8) * GN + col) = pack_f16x2(v2, v3);
            }
        }
    }
}

// ---------------------------------------------------------------------------
// HMMA flash attention: CTA = 128 queries of one head, plain fp16.
// Grid: x = q-block (fast-varying -> the 4 sharers of one head's K/V are
// adjacent, K/V served from L2), y = head.
// ---------------------------------------------------------------------------
constexpr int AST = 72;                       // smem row stride (fp16)
constexpr int SQ = 0;
constexpr int SKV0 = 128 * AST;
constexpr int STG = 2 * 64 * AST;             // per-stage elems (k, v)
constexpr int ATT_DSMEM = (SKV0 + 3 * STG) * 2;  // 73728 B

__global__ __launch_bounds__(256, 2)
void attn_mma(const __half* __restrict__ qg, const __half* __restrict__ kg,
              const __half* __restrict__ vg, __half* __restrict__ og)
{
    extern __shared__ __align__(16) __half smb[];
    const uint32_t sb = smem_to_u32(smb);

    const int tid = threadIdx.x;
    const int wid = tid >> 5;
    const int lid = tid & 31;
    const int m0 = wid * 16;

    const int head = blockIdx.y;
    const int bt = head >> 3;
    const int hk = head & 7;
    const size_t qrow0 = (size_t)bt * 512 + blockIdx.x * 128;
    const size_t krow0 = (size_t)bt * 512;
    const int colb = hk * 64;

    const int seg = lid >> 3, lrow = lid & 7;
    const int a_roff = lrow + ((seg & 1) << 3);
    const int a_coff = (seg >> 1) << 3;
    const int b_roff = lrow + ((seg >> 1) << 3);
    const int b_coff = (seg & 1) << 3;
    const int v_roff = lrow + ((seg & 1) << 3);
    const int v_coff = (seg >> 1) << 3;

    // ---- stage Q (own commit group) ----
    {
#pragma unroll
        for (int t = 0; t < 4; t++) {
            int c = tid + t * 256;              // 1024 chunks
            int r = c >> 3, u = (c & 7) * 8;
            cp_async16(sb + (uint32_t)((SQ + r * AST + u) * 2),
                       qg + (qrow0 + r) * 512 + colb + u);
        }
        CP_COMMIT();
    }
    auto stage_kv = [&](int kt) {
        const size_t kr = krow0 + kt * 64;
        const uint32_t b = SKV0 + (kt % 3) * STG;
#pragma unroll
        for (int t = 0; t < 2; t++) {
            int c = tid + t * 256;              // 512 chunks per array
            int r = c >> 3, u = (c & 7) * 8;
            cp_async16(sb + (uint32_t)((b + r * AST + u) * 2),
                       kg + (kr + r) * 512 + colb + u);
            cp_async16(sb + (uint32_t)((b + 64 * AST + r * AST + u) * 2),
                       vg + (kr + r) * 512 + colb + u);
        }
        CP_COMMIT();
    };

    stage_kv(0);
    stage_kv(1);
    CP_WAIT(2);          // Q complete
    __syncthreads();

    // ---- Q fragments ----
    uint32_t qf[4][4];
#pragma unroll
    for (int ks = 0; ks < 4; ks++)
        ldsm_x4(qf[ks][0], qf[ks][1], qf[ks][2], qf[ks][3],
                sb + (uint32_t)(((SQ + (m0 + a_roff) * AST) + ks * 16 + a_coff) * 2));

    float oacc[8][4];
#pragma unroll
    for (int j = 0; j < 8; j++)
#pragma unroll
        for (int c = 0; c < 4; c++) oacc[j][c] = 0.0f;
    float rs0 = 0.f, rs1 = 0.f;

    for (int kt = 0; kt < 8; kt++) {
        CP_WAIT(1);                 // stage kt ready
        __syncthreads();
        if (kt + 2 < 8) stage_kv(kt + 2);

        const uint32_t base = SKV0 + (kt % 3) * STG;

        // --- S = Q K^T ---
        float sacc[8][4];
#pragma unroll
        for (int j = 0; j < 8; j++)
#pragma unroll
            for (int c = 0; c < 4; c++) sacc[j][c] = 0.0f;

#pragma unroll
        for (int ks = 0; ks < 4; ks++) {
            uint32_t kb[4][4];
#pragma unroll
            for (int j = 0; j < 4; j++)
                ldsm_x4(kb[j][0], kb[j][1], kb[j][2], kb[j][3],
                        sb + (uint32_t)(((base + (j * 16 + b_roff) * AST) + ks * 16 + b_coff) * 2));
#pragma unroll
            for (int j = 0; j < 4; j++) {
                mma16816(sacc[2 * j],     qf[ks], &kb[j][0]);
                mma16816(sacc[2 * j + 1], qf[ks], &kb[j][2]);
            }
        }

        // --- P = exp(S/8), rowsums ---
#pragma unroll
        for (int j = 0; j < 8; j++) {
            sacc[j][0] = __expf(sacc[j][0] * 0.125f);
            sacc[j][1] = __expf(sacc[j][1] * 0.125f);
            sacc[j][2] = __expf(sacc[j][2] * 0.125f);
            sacc[j][3] = __expf(sacc[j][3] * 0.125f);
            rs0 += sacc[j][0] + sacc[j][1];
            rs1 += sacc[j][2] + sacc[j][3];
        }

        // --- O += P V ---
#pragma unroll
        for (int pk = 0; pk < 4; pk++) {
            uint32_t pa[4];
            pa[0] = pack_f16x2(sacc[2 * pk][0],     sacc[2 * pk][1]);
            pa[1] = pack_f16x2(sacc[2 * pk][2],     sacc[2 * pk][3]);
            pa[2] = pack_f16x2(sacc[2 * pk + 1][0], sacc[2 * pk + 1][1]);
            pa[3] = pack_f16x2(sacc[2 * pk + 1][2], sacc[2 * pk + 1][3]);
            uint32_t vb[4][4];
#pragma unroll
            for (int dj = 0; dj < 4; dj++)
                ldsm_x4_t(vb[dj][0], vb[dj][1], vb[dj][2], vb[dj][3],
                          sb + (uint32_t)(((base + 64 * AST + (pk * 16 + v_roff) * AST) + dj * 16 + v_coff) * 2));
#pragma unroll
            for (int dj = 0; dj < 4; dj++) {
                mma16816(oacc[2 * dj],     pa, &vb[dj][0]);
                mma16816(oacc[2 * dj + 1], pa, &vb[dj][2]);
            }
        }
    }

    // --- row-sum reduce across quad lanes ---
    rs0 += __shfl_xor_sync(0xFFFFFFFFu, rs0, 1);
    rs0 += __shfl_xor_sync(0xFFFFFFFFu, rs0, 2);
    rs1 += __shfl_xor_sync(0xFFFFFFFFu, rs1, 1);
    rs1 += __shfl_xor_sync(0xFFFFFFFFu, rs1, 2);
    const float rinv0 = 1.0f / rs0;
    const float rinv1 = 1.0f / rs1;

    // --- normalize + write fp16 ---
    const int gr = lid >> 2;
    const int gc = (lid & 3) * 2;
    const size_t row0 = qrow0 + m0 + gr;
#pragma unroll
    for (int nj = 0; nj < 8; nj++) {
        const int col = colb + nj * 8 + gc;
        *(uint32_t*)(og + row0 * 512 + col) =
            pack_f16x2(oacc[nj][0] * rinv0, oacc[nj][1] * rinv0);
        *(uint32_t*)(og + (row0 + 8) * 512 + col) =
            pack_f16x2(oacc[nj][2] * rinv1, oacc[nj][3] * rinv1);
    }
}

// ---------------------------------------------------------------------------
// Launch
// ---------------------------------------------------------------------------
extern "C" void kernel_launch(void* const* d_in, const int* in_sizes, int n_in,
                              void* d_out, int out_size)
{
    (void)in_sizes; (void)n_in; (void)out_size;
    const float* X  = (const float*)d_in[0];
    const float* Wq = (const float*)d_in[2];
    const float* bq = (const float*)d_in[3];
    const float* Wk = (const float*)d_in[4];
    const float* bk = (const float*)d_in[5];
    const float* Wv = (const float*)d_in[6];
    const float* bv = (const float*)d_in[7];
    const float* W1 = (const float*)d_in[8];
    const float* b1 = (const float*)d_in[9];
    const float* W2 = (const float*)d_in[10];
    const float* b2 = (const float*)d_in[11];
    float* out = (float*)d_out;

    __half *x, *q, *k, *v, *ao, *h, *w2;
    cudaGetSymbolAddress((void**)&x,  g_x);
    cudaGetSymbolAddress((void**)&q,  g_q);
    cudaGetSymbolAddress((void**)&k,  g_k);
    cudaGetSymbolAddress((void**)&v,  g_v);
    cudaGetSymbolAddress((void**)&ao, g_ao);
    cudaGetSymbolAddress((void**)&h,  g_h);
    cudaGetSymbolAddress((void**)&w2, g_w2);
    const size_t WSZ = (size_t)GN * GK;

    cudaFuncSetAttribute((const void*)gemm_mma<true, false, 3>,
                         cudaFuncAttributeMaxDynamicSharedMemorySize, GEMM_DSMEM);
    cudaFuncSetAttribute((const void*)gemm_mma<true, false, 1>,
                         cudaFuncAttributeMaxDynamicSharedMemorySize, GEMM_DSMEM);
    cudaFuncSetAttribute((const void*)gemm_mma<false, true, 1>,
                         cudaFuncAttributeMaxDynamicSharedMemorySize, GEMM_DSMEM);
    cudaFuncSetAttribute((const void*)attn_mma,
                         cudaFuncAttributeMaxDynamicSharedMemorySize, ATT_DSMEM);

    dim3 blk(256);
    dim3 gX((unsigned)((size_t)GM * 64 / 256));
    dim3 gW(512 * 512 / 256, 5);
    dim3 gQKV(3 * GN / BN, GM / BM);    // (12, 384): z fastest for L2 A-reuse
    dim3 gFC(GN / BN, GM / BM);         // (4, 384)
    dim3 gAtt(4, BT * KH);              // (qblock, head): sharers adjacent

    conv_x<<<gX, blk>>>(X, x);
    conv_w5<<<gW, blk>>>(Wq, Wk, Wv, W1, W2, w2);

    // 1) QKV (fp16 out)
    gemm_mma<true, false, 3><<<gQKV, blk, GEMM_DSMEM>>>(x, w2, w2 + WSZ, w2 + 2 * WSZ,
                                                        bq, bk, bv, nullptr, q, k, v);
    // 2) attention -> ao (fp16)
    attn_mma<<<gAtt, blk, ATT_DSMEM>>>(q, k, v, ao);
    // 3) FC1 -> h (fp16, ReLU)
    gemm_mma<true, false, 1><<<gFC, blk, GEMM_DSMEM>>>(ao, w2 + 3 * WSZ, w2 + 3 * WSZ, w2 + 3 * WSZ,
                                                       b1, b1, b1, nullptr, h, h, h);
    // 4) FC2 -> out (fp32)
    gemm_mma<false, true, 1><<<gFC, blk, GEMM_DSMEM>>>(h, w2 + 4 * WSZ, w2 + 4 * WSZ, w2 + 4 * WSZ,
                                                       b2, b2, b2, out,
                                                       nullptr, nullptr, nullptr);
}